// round 1
// baseline (speedup 1.0000x reference)
#include <cuda_runtime.h>
#include <math.h>

#define B_  2
#define S_  2048
#define D_  1024
#define H_  16
#define DK_ 64
#define M_  (B_ * S_)   // 4096 rows

// Scratch (allocation-free rule: __device__ globals)
__device__ float g_q[B_ * H_ * S_ * DK_];
__device__ float g_k[B_ * H_ * S_ * DK_];
__device__ float g_v[B_ * H_ * S_ * DK_];
__device__ float g_ctx[M_ * D_];

// ---------------------------------------------------------------------------
// C = A @ W^T + bias.  A: [M_, 1024] row-major, W: [1024, 1024] row-major.
// headLayout=1: scatter into [B, H, S, DK] scratch; 0: plain [M_, D_].
// 128x128 block tile, BK=8, 256 threads, 8x8 microtile.
// ---------------------------------------------------------------------------
__global__ __launch_bounds__(256) void sgemm_bias(
    const float* __restrict__ A, const float* __restrict__ W,
    const float* __restrict__ bias, float* __restrict__ C, int headLayout)
{
    const int K = D_;
    __shared__ float As[8][128];
    __shared__ float Bs[8][128];

    int tid = threadIdx.x;
    int bm = blockIdx.y * 128;
    int bn = blockIdx.x * 128;

    int lrow = tid >> 1;          // 0..127
    int lcol = (tid & 1) * 4;     // 0 or 4
    const float* Ap = A + (size_t)(bm + lrow) * K + lcol;
    const float* Wp = W + (size_t)(bn + lrow) * K + lcol;

    float acc[8][8];
#pragma unroll
    for (int i = 0; i < 8; i++)
#pragma unroll
        for (int j = 0; j < 8; j++) acc[i][j] = 0.f;

    int mb = (tid >> 4) * 8;
    int nb = (tid & 15) * 8;

    for (int kt = 0; kt < K; kt += 8) {
        float4 av = *(const float4*)(Ap + kt);
        float4 wv = *(const float4*)(Wp + kt);
        As[lcol + 0][lrow] = av.x; As[lcol + 1][lrow] = av.y;
        As[lcol + 2][lrow] = av.z; As[lcol + 3][lrow] = av.w;
        Bs[lcol + 0][lrow] = wv.x; Bs[lcol + 1][lrow] = wv.y;
        Bs[lcol + 2][lrow] = wv.z; Bs[lcol + 3][lrow] = wv.w;
        __syncthreads();
#pragma unroll
        for (int k = 0; k < 8; k++) {
            float a[8], b[8];
#pragma unroll
            for (int i = 0; i < 8; i++) a[i] = As[k][mb + i];
#pragma unroll
            for (int j = 0; j < 8; j++) b[j] = Bs[k][nb + j];
#pragma unroll
            for (int i = 0; i < 8; i++)
#pragma unroll
                for (int j = 0; j < 8; j++) acc[i][j] += a[i] * b[j];
        }
        __syncthreads();
    }

#pragma unroll
    for (int i = 0; i < 8; i++) {
        int m = bm + mb + i;
        int b = m >> 11;            // /S_
        int s = m & (S_ - 1);
#pragma unroll
        for (int j = 0; j < 8; j++) {
            int n = bn + nb + j;
            float v = acc[i][j] + bias[n];
            if (headLayout) {
                int h = n >> 6;
                int dk = n & 63;
                C[(((size_t)b * H_ + h) * S_ + s) * DK_ + dk] = v;
            } else {
                C[(size_t)m * D_ + n] = v;
            }
        }
    }
}

// ---------------------------------------------------------------------------
// Flash attention, fp32, causal, NO 1/sqrt(dk) scaling (matches reference).
// One CTA = one 64-query tile of one (b,h). 256 threads, 4x4 microtile over
// a 64x64 score tile. Q,K stored transposed in smem so inner-loop reads are
// contiguous float4 or broadcast. KP buffer reused: K^T during scores, P
// (row-major) during PV. 48KB static smem.
// ---------------------------------------------------------------------------
__global__ __launch_bounds__(256) void flash_kernel(
    const float* __restrict__ Qh, const float* __restrict__ Kh,
    const float* __restrict__ Vh, float* __restrict__ Ctx)
{
    __shared__ float Qt[64 * 64];   // Qt[dk][row]
    __shared__ float KP[64 * 64];   // Kt[dk][col] -> Ps[row][key]
    __shared__ float Vs[64 * 64];   // Vs[key][dk]

    int qt = blockIdx.x, h = blockIdx.y, b = blockIdx.z;
    int tid = threadIdx.x;
    size_t base = ((size_t)b * H_ + h) * S_ * DK_;
    const float* qg = Qh + base;
    const float* kg = Kh + base;
    const float* vg = Vh + base;
    int q0 = qt * 64;

    // Load Q tile transposed: Qt[c][r]
    {
        int r = tid >> 2;
        int c0 = (tid & 3) * 16;
        const float* gp = qg + (size_t)(q0 + r) * DK_ + c0;
#pragma unroll
        for (int u = 0; u < 4; u++) {
            float4 t = *(const float4*)(gp + 4 * u);
            int c = c0 + 4 * u;
            Qt[(c + 0) * 64 + r] = t.x;
            Qt[(c + 1) * 64 + r] = t.y;
            Qt[(c + 2) * 64 + r] = t.z;
            Qt[(c + 3) * 64 + r] = t.w;
        }
    }

    int ty = tid >> 4;   // 0..15 -> rows 4*ty..4*ty+3
    int tx = tid & 15;   // 0..15 -> cols 4*tx..4*tx+3

    float acc[4][4];
    float mrow[4], lrow[4];
#pragma unroll
    for (int i = 0; i < 4; i++) {
        mrow[i] = -INFINITY; lrow[i] = 0.f;
#pragma unroll
        for (int j = 0; j < 4; j++) acc[i][j] = 0.f;
    }

    for (int kt = 0; kt <= qt; kt++) {
        int k0 = kt * 64;
        __syncthreads();   // previous iter done reading KP/Vs
        {
            int r = tid >> 2;
            int c0 = (tid & 3) * 16;
            const float* kp = kg + (size_t)(k0 + r) * DK_ + c0;
            const float* vp = vg + (size_t)(k0 + r) * DK_ + c0;
#pragma unroll
            for (int u = 0; u < 4; u++) {
                float4 t = *(const float4*)(kp + 4 * u);
                int c = c0 + 4 * u;
                KP[(c + 0) * 64 + r] = t.x;
                KP[(c + 1) * 64 + r] = t.y;
                KP[(c + 2) * 64 + r] = t.z;
                KP[(c + 3) * 64 + r] = t.w;
            }
#pragma unroll
            for (int u = 0; u < 4; u++)
                *(float4*)&Vs[r * 64 + c0 + 4 * u] = *(const float4*)(vp + 4 * u);
        }
        __syncthreads();

        // Scores: s = Q K^T  (64x64x64)
        float s[4][4];
#pragma unroll
        for (int i = 0; i < 4; i++)
#pragma unroll
            for (int j = 0; j < 4; j++) s[i][j] = 0.f;

#pragma unroll 8
        for (int kk = 0; kk < 64; kk++) {
            float4 qa = *(const float4*)&Qt[kk * 64 + 4 * ty];  // broadcast
            float4 ka = *(const float4*)&KP[kk * 64 + 4 * tx];  // contiguous
            float a0 = qa.x, a1 = qa.y, a2 = qa.z, a3 = qa.w;
            float b0 = ka.x, b1 = ka.y, b2 = ka.z, b3 = ka.w;
            s[0][0] += a0 * b0; s[0][1] += a0 * b1; s[0][2] += a0 * b2; s[0][3] += a0 * b3;
            s[1][0] += a1 * b0; s[1][1] += a1 * b1; s[1][2] += a1 * b2; s[1][3] += a1 * b3;
            s[2][0] += a2 * b0; s[2][1] += a2 * b1; s[2][2] += a2 * b2; s[2][3] += a2 * b3;
            s[3][0] += a3 * b0; s[3][1] += a3 * b1; s[3][2] += a3 * b2; s[3][3] += a3 * b3;
        }
        __syncthreads();   // everyone done reading K^T before P overwrites it

        if (kt == qt) {
#pragma unroll
            for (int i = 0; i < 4; i++)
#pragma unroll
                for (int j = 0; j < 4; j++)
                    if (k0 + 4 * tx + j > q0 + 4 * ty + i) s[i][j] = -1e9f;
        }

        // Online softmax update (row owned by 16 lanes sharing ty; width-16 shfl)
#pragma unroll
        for (int i = 0; i < 4; i++) {
            float rm = fmaxf(fmaxf(s[i][0], s[i][1]), fmaxf(s[i][2], s[i][3]));
#pragma unroll
            for (int off = 8; off; off >>= 1)
                rm = fmaxf(rm, __shfl_xor_sync(0xffffffffu, rm, off, 16));
            float mn = fmaxf(mrow[i], rm);
            float rs = 0.f;
#pragma unroll
            for (int j = 0; j < 4; j++) {
                float p = __expf(s[i][j] - mn);
                s[i][j] = p; rs += p;
            }
#pragma unroll
            for (int off = 8; off; off >>= 1)
                rs += __shfl_xor_sync(0xffffffffu, rs, off, 16);
            float sc = __expf(mrow[i] - mn);
            lrow[i] = lrow[i] * sc + rs;
            mrow[i] = mn;
#pragma unroll
            for (int j = 0; j < 4; j++) acc[i][j] *= sc;
            // P row-major: Ps[row][key]
            *(float4*)&KP[(4 * ty + i) * 64 + 4 * tx] =
                make_float4(s[i][0], s[i][1], s[i][2], s[i][3]);
        }
        __syncthreads();

        // acc += P @ V   (64x64x64)
#pragma unroll 8
        for (int kk = 0; kk < 64; kk++) {
            float4 vv = *(const float4*)&Vs[kk * 64 + 4 * tx];   // contiguous
            float p0 = KP[(4 * ty + 0) * 64 + kk];               // broadcast
            float p1 = KP[(4 * ty + 1) * 64 + kk];
            float p2 = KP[(4 * ty + 2) * 64 + kk];
            float p3 = KP[(4 * ty + 3) * 64 + kk];
            acc[0][0] += p0 * vv.x; acc[0][1] += p0 * vv.y; acc[0][2] += p0 * vv.z; acc[0][3] += p0 * vv.w;
            acc[1][0] += p1 * vv.x; acc[1][1] += p1 * vv.y; acc[1][2] += p1 * vv.z; acc[1][3] += p1 * vv.w;
            acc[2][0] += p2 * vv.x; acc[2][1] += p2 * vv.y; acc[2][2] += p2 * vv.z; acc[2][3] += p2 * vv.w;
            acc[3][0] += p3 * vv.x; acc[3][1] += p3 * vv.y; acc[3][2] += p3 * vv.z; acc[3][3] += p3 * vv.w;
        }
    }

    // Epilogue: ctx in [B, S, D] layout for output projection
#pragma unroll
    for (int i = 0; i < 4; i++) {
        float inv = 1.0f / lrow[i];
        int qrow = q0 + 4 * ty + i;
        float4 o = make_float4(acc[i][0] * inv, acc[i][1] * inv,
                               acc[i][2] * inv, acc[i][3] * inv);
        *(float4*)&Ctx[((size_t)b * S_ + qrow) * D_ + h * DK_ + 4 * tx] = o;
    }
}

// ---------------------------------------------------------------------------
extern "C" void kernel_launch(void* const* d_in, const int* in_sizes, int n_in,
                              void* d_out, int out_size)
{
    const float* Q  = (const float*)d_in[0];
    const float* K  = (const float*)d_in[1];
    const float* V  = (const float*)d_in[2];
    // d_in[3] = Mask (tril, hardcoded causal)
    const float* Wq = (const float*)d_in[4];
    const float* bq = (const float*)d_in[5];
    const float* Wk = (const float*)d_in[6];
    const float* bk = (const float*)d_in[7];
    const float* Wv = (const float*)d_in[8];
    const float* bv = (const float*)d_in[9];
    const float* Wo = (const float*)d_in[10];
    const float* bo = (const float*)d_in[11];
    float* out = (float*)d_out;

    float *qp, *kp, *vp, *cp;
    cudaGetSymbolAddress((void**)&qp, g_q);
    cudaGetSymbolAddress((void**)&kp, g_k);
    cudaGetSymbolAddress((void**)&vp, g_v);
    cudaGetSymbolAddress((void**)&cp, g_ctx);

    dim3 gemmGrid(D_ / 128, M_ / 128);   // (8, 32)
    sgemm_bias<<<gemmGrid, 256>>>(Q, Wq, bq, qp, 1);
    sgemm_bias<<<gemmGrid, 256>>>(K, Wk, bk, kp, 1);
    sgemm_bias<<<gemmGrid, 256>>>(V, Wv, bv, vp, 1);

    dim3 attnGrid(S_ / 64, H_, B_);      // (32, 16, 2)
    flash_kernel<<<attnGrid, 256>>>(qp, kp, vp, cp);

    sgemm_bias<<<gemmGrid, 256>>>(cp, Wo, bo, out, 0);
}

// round 3
// speedup vs baseline: 1.8336x; 1.8336x over previous
#include <cuda_runtime.h>
#include <cuda_bf16.h>
#include <math.h>
#include <stdint.h>

#define B_  2
#define S_  2048
#define D_  1024
#define H_  16
#define DK_ 64
#define M_  (B_ * S_)   // 4096 rows

// ---------------------------------------------------------------------------
// Scratch (allocation-free rule: __device__ globals)
// ---------------------------------------------------------------------------
__device__ float g_q[B_ * H_ * S_ * DK_];
__device__ float g_k[B_ * H_ * S_ * DK_];
__device__ float g_v[B_ * H_ * S_ * DK_];
__device__ float g_ctx[M_ * D_];

__device__ __nv_bfloat16 g_ah[M_ * D_];   // activation hi
__device__ __nv_bfloat16 g_al[M_ * D_];   // activation lo
__device__ __nv_bfloat16 g_wh[D_ * D_];   // weight hi
__device__ __nv_bfloat16 g_wl[D_ * D_];   // weight lo

// ---------------------------------------------------------------------------
// helpers (portable sm_80+ ISA only: ldmatrix + mma.sync)
// ---------------------------------------------------------------------------
__device__ __forceinline__ uint32_t smem_u32(const void* p) {
    uint32_t a;
    asm("{ .reg .u64 t; cvta.to.shared.u64 t, %1; cvt.u32.u64 %0, t; }"
        : "=r"(a) : "l"(p));
    return a;
}
__device__ __forceinline__ void ldsm_x4(uint32_t addr, uint32_t* r) {
    asm volatile("ldmatrix.sync.aligned.m8n8.x4.shared.b16 {%0,%1,%2,%3}, [%4];"
        : "=r"(r[0]), "=r"(r[1]), "=r"(r[2]), "=r"(r[3]) : "r"(addr));
}
__device__ __forceinline__ void mma16816(float* d, const uint32_t* a, const uint32_t* b) {
    asm volatile("mma.sync.aligned.m16n8k16.row.col.f32.bf16.bf16.f32 "
        "{%0,%1,%2,%3}, {%4,%5,%6,%7}, {%8,%9}, {%0,%1,%2,%3};"
        : "+f"(d[0]), "+f"(d[1]), "+f"(d[2]), "+f"(d[3])
        : "r"(a[0]), "r"(a[1]), "r"(a[2]), "r"(a[3]), "r"(b[0]), "r"(b[1]));
}
// SW64-style swizzle for 64-byte rows (8 rows x 64B atom)
__device__ __forceinline__ uint32_t swz(uint32_t b) { return b ^ ((b >> 3) & 0x30); }

// ---------------------------------------------------------------------------
// fp32 -> (bf16 hi, bf16 lo) split
// ---------------------------------------------------------------------------
__global__ __launch_bounds__(256) void split_bf16(
    const float* __restrict__ x, __nv_bfloat16* __restrict__ hi,
    __nv_bfloat16* __restrict__ lo, int n)
{
    int i = (blockIdx.x * 256 + threadIdx.x) * 4;
    if (i >= n) return;
    float4 v = *(const float4*)(x + i);
    __nv_bfloat16 h0 = __float2bfloat16(v.x);
    __nv_bfloat16 h1 = __float2bfloat16(v.y);
    __nv_bfloat16 h2 = __float2bfloat16(v.z);
    __nv_bfloat16 h3 = __float2bfloat16(v.w);
    __nv_bfloat16 l0 = __float2bfloat16(v.x - __bfloat162float(h0));
    __nv_bfloat16 l1 = __float2bfloat16(v.y - __bfloat162float(h1));
    __nv_bfloat16 l2 = __float2bfloat16(v.z - __bfloat162float(h2));
    __nv_bfloat16 l3 = __float2bfloat16(v.w - __bfloat162float(h3));
    __nv_bfloat162* hp = (__nv_bfloat162*)(hi + i);
    __nv_bfloat162* lp = (__nv_bfloat162*)(lo + i);
    hp[0] = __nv_bfloat162(h0, h1); hp[1] = __nv_bfloat162(h2, h3);
    lp[0] = __nv_bfloat162(l0, l1); lp[1] = __nv_bfloat162(l2, l3);
}

// ---------------------------------------------------------------------------
// Tensor-core GEMM via mma.sync (bf16 split precision, fp32 accum):
//   C[m][n] = sum_k A[m][k]*W[n][k] + bias[n],
//   A ~ Ah+Al, W ~ Wh+Wl; D = Ah*Wh + Ah*Wl + Al*Wh
// CTA 128x128, 8 warps (2m x 4n), warp tile 64x32, BK=32.
// Smem tiles SW64-swizzled (conflict-free STS.128 + LDSM).
// headLayout=1: scatter into [B,H,S,DK]; 0: plain [M_, D_].
// ---------------------------------------------------------------------------
__global__ __launch_bounds__(256) void mma_gemm(
    const __nv_bfloat16* __restrict__ Ah, const __nv_bfloat16* __restrict__ Al,
    const __nv_bfloat16* __restrict__ Wh, const __nv_bfloat16* __restrict__ Wl,
    const float* __restrict__ bias, float* __restrict__ C, int headLayout)
{
    __shared__ char sm[4 * 8192];   // tiles: 0=Ah 1=Al 2=Wh 3=Wl, each 128x32 bf16

    const uint32_t sb = smem_u32(sm);
    const int tid = threadIdx.x;
    const int lane = tid & 31;
    const int wid = tid >> 5;
    const int bm = blockIdx.y * 128;
    const int bn = blockIdx.x * 128;
    const int wm = (wid & 1) * 64;    // warp row offset
    const int wn = (wid >> 1) * 32;   // warp col offset

    float acc[4][4][4];
#pragma unroll
    for (int mt = 0; mt < 4; mt++)
#pragma unroll
        for (int nt = 0; nt < 4; nt++)
#pragma unroll
            for (int r = 0; r < 4; r++) acc[mt][nt][r] = 0.f;

    // ldmatrix lane addressing (byte offsets before swizzle)
    const int g = lane >> 3, r8 = lane & 7;
    uint32_t rowA[4], rowB[2];
#pragma unroll
    for (int mt = 0; mt < 4; mt++)
        rowA[mt] = (uint32_t)(wm + mt * 16 + (g & 1) * 8 + r8) * 64;
#pragma unroll
    for (int np = 0; np < 2; np++)
        rowB[np] = (uint32_t)(wn + np * 16 + (g >> 1) * 8 + r8) * 64;
    const uint32_t chA = (uint32_t)(g >> 1) * 16;   // A k-chunk select
    const uint32_t chB = (uint32_t)(g & 1) * 16;    // B k-chunk select

    // global load indices (2 x uint4 per tile per thread)
    const int gl_row0 = tid >> 2, gl_c0 = tid & 3;
    const int gl_row1 = (tid + 256) >> 2, gl_c1 = tid & 3;   // +256: same c, row+64
    const uint32_t st0 = swz((uint32_t)gl_row0 * 64 + gl_c0 * 16);
    const uint32_t st1 = swz((uint32_t)gl_row1 * 64 + gl_c1 * 16);

    uint4 pf[4][2];
    const __nv_bfloat16* srcs[4] = { Ah, Al, Wh, Wl };
    const int rbase[4] = { bm, bm, bn, bn };

    // prefetch k-chunk 0
#pragma unroll
    for (int t = 0; t < 4; t++) {
        const __nv_bfloat16* s = srcs[t];
        pf[t][0] = *(const uint4*)(s + (size_t)(rbase[t] + gl_row0) * D_ + gl_c0 * 8);
        pf[t][1] = *(const uint4*)(s + (size_t)(rbase[t] + gl_row1) * D_ + gl_c1 * 8);
    }

    for (int kt = 0; kt < 32; kt++) {
        __syncthreads();   // consumers done with smem
#pragma unroll
        for (int t = 0; t < 4; t++) {
            *(uint4*)(sm + t * 8192 + st0) = pf[t][0];
            *(uint4*)(sm + t * 8192 + st1) = pf[t][1];
        }
        __syncthreads();

        if (kt + 1 < 32) {
            const int k0 = (kt + 1) * 32;
#pragma unroll
            for (int t = 0; t < 4; t++) {
                const __nv_bfloat16* s = srcs[t];
                pf[t][0] = *(const uint4*)(s + (size_t)(rbase[t] + gl_row0) * D_ + k0 + gl_c0 * 8);
                pf[t][1] = *(const uint4*)(s + (size_t)(rbase[t] + gl_row1) * D_ + k0 + gl_c1 * 8);
            }
        }

#pragma unroll
        for (int ks = 0; ks < 2; ks++) {
            const uint32_t kb = (uint32_t)ks * 32;   // k16 step = 2 chunks = 32B
            uint32_t ah[4][4], al[4][4], bh[4][2], bl[4][2];
#pragma unroll
            for (int mt = 0; mt < 4; mt++) {
                uint32_t b = rowA[mt] + kb + chA;
                uint32_t a = sb + swz(b);
                ldsm_x4(a, ah[mt]);
                ldsm_x4(a + 8192, al[mt]);
            }
#pragma unroll
            for (int np = 0; np < 2; np++) {
                uint32_t b = rowB[np] + kb + chB;
                uint32_t a = sb + 2 * 8192 + swz(b);
                uint32_t q[4];
                ldsm_x4(a, q);
                bh[2 * np][0] = q[0]; bh[2 * np][1] = q[1];
                bh[2 * np + 1][0] = q[2]; bh[2 * np + 1][1] = q[3];
                ldsm_x4(a + 8192, q);
                bl[2 * np][0] = q[0]; bl[2 * np][1] = q[1];
                bl[2 * np + 1][0] = q[2]; bl[2 * np + 1][1] = q[3];
            }
#pragma unroll
            for (int mt = 0; mt < 4; mt++)
#pragma unroll
                for (int nt = 0; nt < 4; nt++) {
                    mma16816(acc[mt][nt], ah[mt], bh[nt]);
                    mma16816(acc[mt][nt], ah[mt], bl[nt]);
                    mma16816(acc[mt][nt], al[mt], bh[nt]);
                }
        }
    }

    // ---- epilogue: fragment -> global with bias ----
    const int fr = lane >> 2;          // fragment row 0..7
    const int fc = (lane & 3) * 2;     // fragment col 0,2,4,6
#pragma unroll
    for (int mt = 0; mt < 4; mt++) {
#pragma unroll
        for (int nt = 0; nt < 4; nt++) {
            int col = bn + wn + nt * 8 + fc;
            float bx = bias[col], by = bias[col + 1];
#pragma unroll
            for (int half = 0; half < 2; half++) {
                int row = bm + wm + mt * 16 + fr + half * 8;
                float2 v = make_float2(acc[mt][nt][2 * half] + bx,
                                       acc[mt][nt][2 * half + 1] + by);
                if (headLayout) {
                    int b = row >> 11, s = row & (S_ - 1);
                    int h = col >> 6, dk = col & 63;
                    *(float2*)&C[(((size_t)b * H_ + h) * S_ + s) * DK_ + dk] = v;
                } else {
                    *(float2*)&C[(size_t)row * D_ + col] = v;
                }
            }
        }
    }
}

// ---------------------------------------------------------------------------
// Flash attention, fp32, causal, NO 1/sqrt(dk) scaling (matches reference).
// (unchanged from R1 — R4 target)
// ---------------------------------------------------------------------------
__global__ __launch_bounds__(256) void flash_kernel(
    const float* __restrict__ Qh, const float* __restrict__ Kh,
    const float* __restrict__ Vh, float* __restrict__ Ctx)
{
    __shared__ float Qt[64 * 64];
    __shared__ float KP[64 * 64];
    __shared__ float Vs[64 * 64];

    int qt = blockIdx.x, h = blockIdx.y, b = blockIdx.z;
    int tid = threadIdx.x;
    size_t base = ((size_t)b * H_ + h) * S_ * DK_;
    const float* qg = Qh + base;
    const float* kg = Kh + base;
    const float* vg = Vh + base;
    int q0 = qt * 64;

    {
        int r = tid >> 2;
        int c0 = (tid & 3) * 16;
        const float* gp = qg + (size_t)(q0 + r) * DK_ + c0;
#pragma unroll
        for (int u = 0; u < 4; u++) {
            float4 t = *(const float4*)(gp + 4 * u);
            int c = c0 + 4 * u;
            Qt[(c + 0) * 64 + r] = t.x;
            Qt[(c + 1) * 64 + r] = t.y;
            Qt[(c + 2) * 64 + r] = t.z;
            Qt[(c + 3) * 64 + r] = t.w;
        }
    }

    int ty = tid >> 4;
    int tx = tid & 15;

    float acc[4][4];
    float mrow[4], lrow[4];
#pragma unroll
    for (int i = 0; i < 4; i++) {
        mrow[i] = -INFINITY; lrow[i] = 0.f;
#pragma unroll
        for (int j = 0; j < 4; j++) acc[i][j] = 0.f;
    }

    for (int kt = 0; kt <= qt; kt++) {
        int k0 = kt * 64;
        __syncthreads();
        {
            int r = tid >> 2;
            int c0 = (tid & 3) * 16;
            const float* kp = kg + (size_t)(k0 + r) * DK_ + c0;
            const float* vp = vg + (size_t)(k0 + r) * DK_ + c0;
#pragma unroll
            for (int u = 0; u < 4; u++) {
                float4 t = *(const float4*)(kp + 4 * u);
                int c = c0 + 4 * u;
                KP[(c + 0) * 64 + r] = t.x;
                KP[(c + 1) * 64 + r] = t.y;
                KP[(c + 2) * 64 + r] = t.z;
                KP[(c + 3) * 64 + r] = t.w;
            }
#pragma unroll
            for (int u = 0; u < 4; u++)
                *(float4*)&Vs[r * 64 + c0 + 4 * u] = *(const float4*)(vp + 4 * u);
        }
        __syncthreads();

        float s[4][4];
#pragma unroll
        for (int i = 0; i < 4; i++)
#pragma unroll
            for (int j = 0; j < 4; j++) s[i][j] = 0.f;

#pragma unroll 8
        for (int kk = 0; kk < 64; kk++) {
            float4 qa = *(const float4*)&Qt[kk * 64 + 4 * ty];
            float4 ka = *(const float4*)&KP[kk * 64 + 4 * tx];
            float a0 = qa.x, a1 = qa.y, a2 = qa.z, a3 = qa.w;
            float b0 = ka.x, b1 = ka.y, b2 = ka.z, b3 = ka.w;
            s[0][0] += a0 * b0; s[0][1] += a0 * b1; s[0][2] += a0 * b2; s[0][3] += a0 * b3;
            s[1][0] += a1 * b0; s[1][1] += a1 * b1; s[1][2] += a1 * b2; s[1][3] += a1 * b3;
            s[2][0] += a2 * b0; s[2][1] += a2 * b1; s[2][2] += a2 * b2; s[2][3] += a2 * b3;
            s[3][0] += a3 * b0; s[3][1] += a3 * b1; s[3][2] += a3 * b2; s[3][3] += a3 * b3;
        }
        __syncthreads();

        if (kt == qt) {
#pragma unroll
            for (int i = 0; i < 4; i++)
#pragma unroll
                for (int j = 0; j < 4; j++)
                    if (k0 + 4 * tx + j > q0 + 4 * ty + i) s[i][j] = -1e9f;
        }

#pragma unroll
        for (int i = 0; i < 4; i++) {
            float rm = fmaxf(fmaxf(s[i][0], s[i][1]), fmaxf(s[i][2], s[i][3]));
#pragma unroll
            for (int off = 8; off; off >>= 1)
                rm = fmaxf(rm, __shfl_xor_sync(0xffffffffu, rm, off, 16));
            float mn = fmaxf(mrow[i], rm);
            float rs = 0.f;
#pragma unroll
            for (int j = 0; j < 4; j++) {
                float p = __expf(s[i][j] - mn);
                s[i][j] = p; rs += p;
            }
#pragma unroll
            for (int off = 8; off; off >>= 1)
                rs += __shfl_xor_sync(0xffffffffu, rs, off, 16);
            float sc = __expf(mrow[i] - mn);
            lrow[i] = lrow[i] * sc + rs;
            mrow[i] = mn;
#pragma unroll
            for (int j = 0; j < 4; j++) acc[i][j] *= sc;
            *(float4*)&KP[(4 * ty + i) * 64 + 4 * tx] =
                make_float4(s[i][0], s[i][1], s[i][2], s[i][3]);
        }
        __syncthreads();

#pragma unroll 8
        for (int kk = 0; kk < 64; kk++) {
            float4 vv = *(const float4*)&Vs[kk * 64 + 4 * tx];
            float p0 = KP[(4 * ty + 0) * 64 + kk];
            float p1 = KP[(4 * ty + 1) * 64 + kk];
            float p2 = KP[(4 * ty + 2) * 64 + kk];
            float p3 = KP[(4 * ty + 3) * 64 + kk];
            acc[0][0] += p0 * vv.x; acc[0][1] += p0 * vv.y; acc[0][2] += p0 * vv.z; acc[0][3] += p0 * vv.w;
            acc[1][0] += p1 * vv.x; acc[1][1] += p1 * vv.y; acc[1][2] += p1 * vv.z; acc[1][3] += p1 * vv.w;
            acc[2][0] += p2 * vv.x; acc[2][1] += p2 * vv.y; acc[2][2] += p2 * vv.z; acc[2][3] += p2 * vv.w;
            acc[3][0] += p3 * vv.x; acc[3][1] += p3 * vv.y; acc[3][2] += p3 * vv.z; acc[3][3] += p3 * vv.w;
        }
    }

#pragma unroll
    for (int i = 0; i < 4; i++) {
        float inv = 1.0f / lrow[i];
        int qrow = q0 + 4 * ty + i;
        float4 o = make_float4(acc[i][0] * inv, acc[i][1] * inv,
                               acc[i][2] * inv, acc[i][3] * inv);
        *(float4*)&Ctx[((size_t)b * S_ + qrow) * D_ + h * DK_ + 4 * tx] = o;
    }
}

// ---------------------------------------------------------------------------
extern "C" void kernel_launch(void* const* d_in, const int* in_sizes, int n_in,
                              void* d_out, int out_size)
{
    const float* Q  = (const float*)d_in[0];
    const float* K  = (const float*)d_in[1];
    const float* V  = (const float*)d_in[2];
    // d_in[3] = Mask (guaranteed tril -> hardcoded causal)
    const float* Wq = (const float*)d_in[4];
    const float* bq = (const float*)d_in[5];
    const float* Wk = (const float*)d_in[6];
    const float* bk = (const float*)d_in[7];
    const float* Wv = (const float*)d_in[8];
    const float* bv = (const float*)d_in[9];
    const float* Wo = (const float*)d_in[10];
    const float* bo = (const float*)d_in[11];
    float* out = (float*)d_out;

    float *qp, *kp, *vp, *cp;
    cudaGetSymbolAddress((void**)&qp, g_q);
    cudaGetSymbolAddress((void**)&kp, g_k);
    cudaGetSymbolAddress((void**)&vp, g_v);
    cudaGetSymbolAddress((void**)&cp, g_ctx);
    __nv_bfloat16 *ah, *al, *wh, *wl;
    cudaGetSymbolAddress((void**)&ah, g_ah);
    cudaGetSymbolAddress((void**)&al, g_al);
    cudaGetSymbolAddress((void**)&wh, g_wh);
    cudaGetSymbolAddress((void**)&wl, g_wl);

    const int nA = M_ * D_;       // 4194304
    const int nW = D_ * D_;       // 1048576
    dim3 gemmGrid(D_ / 128, M_ / 128);   // (8, 32)

    // Q projection
    split_bf16<<<nA / 1024, 256>>>(Q, ah, al, nA);
    split_bf16<<<nW / 1024, 256>>>(Wq, wh, wl, nW);
    mma_gemm<<<gemmGrid, 256>>>(ah, al, wh, wl, bq, qp, 1);
    // K projection
    split_bf16<<<nA / 1024, 256>>>(K, ah, al, nA);
    split_bf16<<<nW / 1024, 256>>>(Wk, wh, wl, nW);
    mma_gemm<<<gemmGrid, 256>>>(ah, al, wh, wl, bk, kp, 1);
    // V projection
    split_bf16<<<nA / 1024, 256>>>(V, ah, al, nA);
    split_bf16<<<nW / 1024, 256>>>(Wv, wh, wl, nW);
    mma_gemm<<<gemmGrid, 256>>>(ah, al, wh, wl, bv, vp, 1);

    // attention
    dim3 attnGrid(S_ / 64, H_, B_);      // (32, 16, 2)
    flash_kernel<<<attnGrid, 256>>>(qp, kp, vp, cp);

    // output projection
    split_bf16<<<nA / 1024, 256>>>(cp, ah, al, nA);
    split_bf16<<<nW / 1024, 256>>>(Wo, wh, wl, nW);
    mma_gemm<<<gemmGrid, 256>>>(ah, al, wh, wl, bo, out, 0);
}

// round 4
// speedup vs baseline: 3.3202x; 1.8107x over previous
#include <cuda_runtime.h>
#include <cuda_bf16.h>
#include <math.h>
#include <stdint.h>

#define B_  2
#define S_  2048
#define D_  1024
#define H_  16
#define DK_ 64
#define M_  (B_ * S_)   // 4096 rows

// ---------------------------------------------------------------------------
// Scratch (allocation-free rule: __device__ globals)
// ---------------------------------------------------------------------------
__device__ __nv_bfloat16 g_ah[M_ * D_];   // activation hi (GEMM A / ctx out)
__device__ __nv_bfloat16 g_al[M_ * D_];   // activation lo
__device__ __nv_bfloat16 g_wh[D_ * D_];   // weight hi
__device__ __nv_bfloat16 g_wl[D_ * D_];   // weight lo
__device__ __nv_bfloat16 g_qh[B_ * H_ * S_ * DK_];
__device__ __nv_bfloat16 g_ql[B_ * H_ * S_ * DK_];
__device__ __nv_bfloat16 g_kh[B_ * H_ * S_ * DK_];
__device__ __nv_bfloat16 g_kl[B_ * H_ * S_ * DK_];
__device__ __nv_bfloat16 g_vh[B_ * H_ * S_ * DK_];
__device__ __nv_bfloat16 g_vl[B_ * H_ * S_ * DK_];

// ---------------------------------------------------------------------------
// helpers (portable sm_80+ ISA: ldmatrix + mma.sync)
// ---------------------------------------------------------------------------
__device__ __forceinline__ uint32_t smem_u32(const void* p) {
    uint32_t a;
    asm("{ .reg .u64 t; cvta.to.shared.u64 t, %1; cvt.u32.u64 %0, t; }"
        : "=r"(a) : "l"(p));
    return a;
}
__device__ __forceinline__ void ldsm_x4(uint32_t addr, uint32_t* r) {
    asm volatile("ldmatrix.sync.aligned.m8n8.x4.shared.b16 {%0,%1,%2,%3}, [%4];"
        : "=r"(r[0]), "=r"(r[1]), "=r"(r[2]), "=r"(r[3]) : "r"(addr));
}
__device__ __forceinline__ void ldsm_x4_t(uint32_t addr, uint32_t* r) {
    asm volatile("ldmatrix.sync.aligned.m8n8.x4.trans.shared.b16 {%0,%1,%2,%3}, [%4];"
        : "=r"(r[0]), "=r"(r[1]), "=r"(r[2]), "=r"(r[3]) : "r"(addr));
}
__device__ __forceinline__ void mma16816(float* d, const uint32_t* a, const uint32_t* b) {
    asm volatile("mma.sync.aligned.m16n8k16.row.col.f32.bf16.bf16.f32 "
        "{%0,%1,%2,%3}, {%4,%5,%6,%7}, {%8,%9}, {%0,%1,%2,%3};"
        : "+f"(d[0]), "+f"(d[1]), "+f"(d[2]), "+f"(d[3])
        : "r"(a[0]), "r"(a[1]), "r"(a[2]), "r"(a[3]), "r"(b[0]), "r"(b[1]));
}
__device__ __forceinline__ uint32_t swz64(uint32_t b)  { return b ^ ((b >> 3) & 0x30); }
__device__ __forceinline__ uint32_t swz128(uint32_t b) { return b ^ ((b >> 3) & 0x70); }
__device__ __forceinline__ uint32_t pack2(float x, float y) {
    __nv_bfloat162 t = __floats2bfloat162_rn(x, y);
    return *(uint32_t*)&t;
}
__device__ __forceinline__ void split1(float v, __nv_bfloat16& h, __nv_bfloat16& l) {
    h = __float2bfloat16(v);
    l = __float2bfloat16(v - __bfloat162float(h));
}

// ---------------------------------------------------------------------------
// fp32 -> (bf16 hi, bf16 lo) split
// ---------------------------------------------------------------------------
__global__ __launch_bounds__(256) void split_bf16(
    const float* __restrict__ x, __nv_bfloat16* __restrict__ hi,
    __nv_bfloat16* __restrict__ lo, int n)
{
    int i = (blockIdx.x * 256 + threadIdx.x) * 4;
    if (i >= n) return;
    float4 v = *(const float4*)(x + i);
    __nv_bfloat16 h0, h1, h2, h3, l0, l1, l2, l3;
    split1(v.x, h0, l0); split1(v.y, h1, l1);
    split1(v.z, h2, l2); split1(v.w, h3, l3);
    __nv_bfloat162* hp = (__nv_bfloat162*)(hi + i);
    __nv_bfloat162* lp = (__nv_bfloat162*)(lo + i);
    hp[0] = __nv_bfloat162(h0, h1); hp[1] = __nv_bfloat162(h2, h3);
    lp[0] = __nv_bfloat162(l0, l1); lp[1] = __nv_bfloat162(l2, l3);
}

// ---------------------------------------------------------------------------
// Tensor-core GEMM (split bf16):  C[m][n] = sum_k A[m][k]*W[n][k] + bias[n]
// CTA 128x128, 8 warps (2m x 4n), warp tile 64x32, BK=32, SW64 smem swizzle.
// mode=1: write bf16 hi/lo at [B,H,S,DK] layout; mode=0: fp32 flat [M_,D_].
// ---------------------------------------------------------------------------
__global__ __launch_bounds__(256) void mma_gemm(
    const __nv_bfloat16* __restrict__ Ah, const __nv_bfloat16* __restrict__ Al,
    const __nv_bfloat16* __restrict__ Wh, const __nv_bfloat16* __restrict__ Wl,
    const float* __restrict__ bias,
    __nv_bfloat16* __restrict__ Chi, __nv_bfloat16* __restrict__ Clo,
    float* __restrict__ Cf, int mode)
{
    __shared__ char sm[4 * 8192];   // Ah, Al, Wh, Wl tiles: 128x32 bf16 each

    const uint32_t sb = smem_u32(sm);
    const int tid = threadIdx.x;
    const int lane = tid & 31;
    const int wid = tid >> 5;
    const int bm = blockIdx.y * 128;
    const int bn = blockIdx.x * 128;
    const int wm = (wid & 1) * 64;
    const int wn = (wid >> 1) * 32;

    float acc[4][4][4];
#pragma unroll
    for (int mt = 0; mt < 4; mt++)
#pragma unroll
        for (int nt = 0; nt < 4; nt++)
#pragma unroll
            for (int r = 0; r < 4; r++) acc[mt][nt][r] = 0.f;

    const int g = lane >> 3, r8 = lane & 7;
    uint32_t rowA[4], rowB[2];
#pragma unroll
    for (int mt = 0; mt < 4; mt++)
        rowA[mt] = (uint32_t)(wm + mt * 16 + (g & 1) * 8 + r8) * 64;
#pragma unroll
    for (int np = 0; np < 2; np++)
        rowB[np] = (uint32_t)(wn + np * 16 + (g >> 1) * 8 + r8) * 64;
    const uint32_t chA = (uint32_t)(g >> 1) * 16;
    const uint32_t chB = (uint32_t)(g & 1) * 16;

    const int gl_row0 = tid >> 2, gl_c0 = tid & 3;
    const int gl_row1 = (tid + 256) >> 2, gl_c1 = tid & 3;
    const uint32_t st0 = swz64((uint32_t)gl_row0 * 64 + gl_c0 * 16);
    const uint32_t st1 = swz64((uint32_t)gl_row1 * 64 + gl_c1 * 16);

    uint4 pf[4][2];
    const __nv_bfloat16* srcs[4] = { Ah, Al, Wh, Wl };
    const int rbase[4] = { bm, bm, bn, bn };

#pragma unroll
    for (int t = 0; t < 4; t++) {
        const __nv_bfloat16* s = srcs[t];
        pf[t][0] = *(const uint4*)(s + (size_t)(rbase[t] + gl_row0) * D_ + gl_c0 * 8);
        pf[t][1] = *(const uint4*)(s + (size_t)(rbase[t] + gl_row1) * D_ + gl_c1 * 8);
    }

    for (int kt = 0; kt < 32; kt++) {
        __syncthreads();
#pragma unroll
        for (int t = 0; t < 4; t++) {
            *(uint4*)(sm + t * 8192 + st0) = pf[t][0];
            *(uint4*)(sm + t * 8192 + st1) = pf[t][1];
        }
        __syncthreads();

        if (kt + 1 < 32) {
            const int k0 = (kt + 1) * 32;
#pragma unroll
            for (int t = 0; t < 4; t++) {
                const __nv_bfloat16* s = srcs[t];
                pf[t][0] = *(const uint4*)(s + (size_t)(rbase[t] + gl_row0) * D_ + k0 + gl_c0 * 8);
                pf[t][1] = *(const uint4*)(s + (size_t)(rbase[t] + gl_row1) * D_ + k0 + gl_c1 * 8);
            }
        }

#pragma unroll
        for (int ks = 0; ks < 2; ks++) {
            const uint32_t kb = (uint32_t)ks * 32;
            uint32_t ah[4][4], al[4][4], bh[4][2], bl[4][2];
#pragma unroll
            for (int mt = 0; mt < 4; mt++) {
                uint32_t a = sb + swz64(rowA[mt] + kb + chA);
                ldsm_x4(a, ah[mt]);
                ldsm_x4(a + 8192, al[mt]);
            }
#pragma unroll
            for (int np = 0; np < 2; np++) {
                uint32_t a = sb + 2 * 8192 + swz64(rowB[np] + kb + chB);
                uint32_t q[4];
                ldsm_x4(a, q);
                bh[2 * np][0] = q[0]; bh[2 * np][1] = q[1];
                bh[2 * np + 1][0] = q[2]; bh[2 * np + 1][1] = q[3];
                ldsm_x4(a + 8192, q);
                bl[2 * np][0] = q[0]; bl[2 * np][1] = q[1];
                bl[2 * np + 1][0] = q[2]; bl[2 * np + 1][1] = q[3];
            }
#pragma unroll
            for (int mt = 0; mt < 4; mt++)
#pragma unroll
                for (int nt = 0; nt < 4; nt++) {
                    mma16816(acc[mt][nt], ah[mt], bh[nt]);
                    mma16816(acc[mt][nt], ah[mt], bl[nt]);
                    mma16816(acc[mt][nt], al[mt], bh[nt]);
                }
        }
    }

    const int fr = lane >> 2;
    const int fc = (lane & 3) * 2;
#pragma unroll
    for (int mt = 0; mt < 4; mt++) {
#pragma unroll
        for (int nt = 0; nt < 4; nt++) {
            int col = bn + wn + nt * 8 + fc;
            float bx = bias[col], by = bias[col + 1];
#pragma unroll
            for (int half = 0; half < 2; half++) {
                int row = bm + wm + mt * 16 + fr + half * 8;
                float vx = acc[mt][nt][2 * half] + bx;
                float vy = acc[mt][nt][2 * half + 1] + by;
                if (mode) {
                    int b = row >> 11, s = row & (S_ - 1);
                    int h = col >> 6, dk = col & 63;
                    size_t o = (((size_t)b * H_ + h) * S_ + s) * DK_ + dk;
                    __nv_bfloat16 hx, hy, lx, ly;
                    split1(vx, hx, lx); split1(vy, hy, ly);
                    *(__nv_bfloat162*)&Chi[o] = __nv_bfloat162(hx, hy);
                    *(__nv_bfloat162*)&Clo[o] = __nv_bfloat162(lx, ly);
                } else {
                    *(float2*)&Cf[(size_t)row * D_ + col] = make_float2(vx, vy);
                }
            }
        }
    }
}

// ---------------------------------------------------------------------------
// Flash attention on mma.sync, split bf16, fp32 accum, causal, unscaled.
// CTA = 128 q-rows of one (b,h). 8 warps x 16 rows. K-tile = 64 keys.
// P stays in registers (S-accum fragment == A fragment layout).
// Writes ctx as bf16 hi/lo into the out-projection A buffers at [b*S+s][D].
// ---------------------------------------------------------------------------
#define FQH 0
#define FQL 16384
#define FKH 32768
#define FSM_TOTAL 65536    // QH,QL 16KB each + KH,KL,VH,VL 8KB each

__global__ __launch_bounds__(256, 2) void flash_mma(
    const __nv_bfloat16* __restrict__ Qh, const __nv_bfloat16* __restrict__ Ql,
    const __nv_bfloat16* __restrict__ Kh, const __nv_bfloat16* __restrict__ Kl,
    const __nv_bfloat16* __restrict__ Vh, const __nv_bfloat16* __restrict__ Vl,
    __nv_bfloat16* __restrict__ OutH, __nv_bfloat16* __restrict__ OutL)
{
    extern __shared__ char fsm[];
    const uint32_t sb = smem_u32(fsm);
    const int tid = threadIdx.x;
    const int lane = tid & 31;
    const int w = tid >> 5;
    const int bx = blockIdx.x, h = blockIdx.y, b = blockIdx.z;
    const size_t base = ((size_t)b * H_ + h) * S_ * DK_;
    const int q0 = bx * 128;

    // ---- load Q tiles hi/lo (128 rows x 64 bf16), swizzled 128B rows ----
#pragma unroll
    for (int i = 0; i < 4; i++) {
        int idx = i * 256 + tid;            // 0..1023
        int row = idx >> 3, ch = idx & 7;
        uint4 vh_ = *(const uint4*)(Qh + base + (size_t)(q0 + row) * DK_ + ch * 8);
        uint4 vl_ = *(const uint4*)(Ql + base + (size_t)(q0 + row) * DK_ + ch * 8);
        uint32_t sw = swz128((uint32_t)row * 128 + ch * 16);
        *(uint4*)(fsm + FQH + sw) = vh_;
        *(uint4*)(fsm + FQL + sw) = vl_;
    }

    float o[8][4];
#pragma unroll
    for (int nt = 0; nt < 8; nt++)
#pragma unroll
        for (int r = 0; r < 4; r++) o[nt][r] = 0.f;
    float m0 = -INFINITY, m1 = -INFINITY, l0 = 0.f, l1 = 0.f;

    const int g = lane >> 3, r8 = lane & 7;
    // A (Q) frag addressing: rows w*16 + (g&1)*8 + r8, k-col (g>>1)*16
    const uint32_t qrow = (uint32_t)(w * 16 + (g & 1) * 8 + r8) * 128 + (uint32_t)(g >> 1) * 16;
    // B (K) frag: rows np*16 + (g>>1)*8 + r8, k-col (g&1)*16
    const uint32_t krow = (uint32_t)((g >> 1) * 8 + r8) * 128 + (uint32_t)(g & 1) * 16;
    // V trans frag: rows (lane&7) + ((lane>>3)&1)*8, dk-col (lane>>4)*16
    const uint32_t vrow = (uint32_t)((lane & 7) + ((lane >> 3) & 1) * 8) * 128
                        + (uint32_t)(lane >> 4) * 16;

    const int nkt = 2 * bx + 2;
    const int wq = q0 + w * 16;          // warp's first q row

    for (int kt = 0; kt < nkt; kt++) {
        const int k0 = kt * 64;
        __syncthreads();
        // ---- load K/V hi/lo tiles (4 x 64 rows x 64 bf16) ----
#pragma unroll
        for (int t = 0; t < 8; t++) {
            const __nv_bfloat16* src = (t < 2) ? ((t & 1) ? Kl : Kh)
                                               : ((t & 1) ? Vl : Vh);
            src += base;
            int c = ((t & 1) ? 256 : 0) + 0;   // placeholder
            (void)c;
            int tensor = t >> 1;
            int ci = (t & 1) * 256 + tid;      // 0..511
            int row = ci >> 3, ch = ci & 7;
            const __nv_bfloat16* s2 = (tensor == 0) ? Kh : (tensor == 1) ? Kl
                                     : (tensor == 2) ? Vh : Vl;
            uint4 val = *(const uint4*)(s2 + base + (size_t)(k0 + row) * DK_ + ch * 8);
            uint32_t sw = swz128((uint32_t)row * 128 + ch * 16);
            *(uint4*)(fsm + FKH + tensor * 8192 + sw) = val;
        }
        __syncthreads();

        // ---- S = Q K^T (128x64 per CTA, 16x64 per warp) ----
        float s[8][4];
#pragma unroll
        for (int nt = 0; nt < 8; nt++)
#pragma unroll
            for (int r = 0; r < 4; r++) s[nt][r] = 0.f;

#pragma unroll
        for (int ks = 0; ks < 4; ks++) {
            uint32_t qh_f[4], ql_f[4];
            uint32_t qa = sb + FQH + swz128(qrow + ks * 32);
            ldsm_x4(qa, qh_f);
            ldsm_x4(qa + (FQL - FQH), ql_f);
#pragma unroll
            for (int np = 0; np < 4; np++) {
                uint32_t ka = sb + FKH + swz128(krow + (uint32_t)np * 16 * 128 + ks * 32);
                uint32_t qh_[4], ql_[4];
                ldsm_x4(ka, qh_);
                ldsm_x4(ka + 8192, ql_);
                uint32_t bh0[2] = { qh_[0], qh_[1] }, bh1[2] = { qh_[2], qh_[3] };
                uint32_t bl0[2] = { ql_[0], ql_[1] }, bl1[2] = { ql_[2], ql_[3] };
                mma16816(s[2 * np],     qh_f, bh0);
                mma16816(s[2 * np],     qh_f, bl0);
                mma16816(s[2 * np],     ql_f, bh0);
                mma16816(s[2 * np + 1], qh_f, bh1);
                mma16816(s[2 * np + 1], qh_f, bl1);
                mma16816(s[2 * np + 1], ql_f, bh1);
            }
        }

        // ---- causal mask (only diagonal-region tiles) ----
        if (k0 + 63 > wq) {
            int r0g = wq + (lane >> 2), r1g = r0g + 8;
            int cb = k0 + 2 * (lane & 3);
#pragma unroll
            for (int nt = 0; nt < 8; nt++) {
                int key = cb + nt * 8;
                if (key     > r0g) s[nt][0] = -1e9f;
                if (key + 1 > r0g) s[nt][1] = -1e9f;
                if (key     > r1g) s[nt][2] = -1e9f;
                if (key + 1 > r1g) s[nt][3] = -1e9f;
            }
        }

        // ---- online softmax ----
        float rm0 = -INFINITY, rm1 = -INFINITY;
#pragma unroll
        for (int nt = 0; nt < 8; nt++) {
            rm0 = fmaxf(rm0, fmaxf(s[nt][0], s[nt][1]));
            rm1 = fmaxf(rm1, fmaxf(s[nt][2], s[nt][3]));
        }
        rm0 = fmaxf(rm0, __shfl_xor_sync(0xffffffffu, rm0, 1));
        rm0 = fmaxf(rm0, __shfl_xor_sync(0xffffffffu, rm0, 2));
        rm1 = fmaxf(rm1, __shfl_xor_sync(0xffffffffu, rm1, 1));
        rm1 = fmaxf(rm1, __shfl_xor_sync(0xffffffffu, rm1, 2));
        float mn0 = fmaxf(m0, rm0), mn1 = fmaxf(m1, rm1);
        float sc0 = __expf(m0 - mn0), sc1 = __expf(m1 - mn1);
        float rs0 = 0.f, rs1 = 0.f;
#pragma unroll
        for (int nt = 0; nt < 8; nt++) {
            s[nt][0] = __expf(s[nt][0] - mn0);
            s[nt][1] = __expf(s[nt][1] - mn0);
            s[nt][2] = __expf(s[nt][2] - mn1);
            s[nt][3] = __expf(s[nt][3] - mn1);
            rs0 += s[nt][0] + s[nt][1];
            rs1 += s[nt][2] + s[nt][3];
        }
        rs0 += __shfl_xor_sync(0xffffffffu, rs0, 1);
        rs0 += __shfl_xor_sync(0xffffffffu, rs0, 2);
        rs1 += __shfl_xor_sync(0xffffffffu, rs1, 1);
        rs1 += __shfl_xor_sync(0xffffffffu, rs1, 2);
        l0 = l0 * sc0 + rs0; m0 = mn0;
        l1 = l1 * sc1 + rs1; m1 = mn1;
#pragma unroll
        for (int nt = 0; nt < 8; nt++) {
            o[nt][0] *= sc0; o[nt][1] *= sc0;
            o[nt][2] *= sc1; o[nt][3] *= sc1;
        }

        // ---- O += P V  (P from registers, split hi/lo) ----
#pragma unroll
        for (int ks = 0; ks < 4; ks++) {
            uint32_t aph[4], apl[4];
#pragma unroll
            for (int half = 0; half < 2; half++) {
                int st = 2 * ks + half;
                __nv_bfloat16 h0_, l0_, h1_, l1_, h2_, l2_, h3_, l3_;
                split1(s[st][0], h0_, l0_); split1(s[st][1], h1_, l1_);
                split1(s[st][2], h2_, l2_); split1(s[st][3], h3_, l3_);
                __nv_bfloat162 ph01(h0_, h1_), pl01(l0_, l1_);
                __nv_bfloat162 ph23(h2_, h3_), pl23(l2_, l3_);
                aph[2 * half]     = *(uint32_t*)&ph01;
                aph[2 * half + 1] = *(uint32_t*)&ph23;
                apl[2 * half]     = *(uint32_t*)&pl01;
                apl[2 * half + 1] = *(uint32_t*)&pl23;
            }
            // reorder: a0=rows r k0-7, a1=rows r+8 k0-7, a2=rows r k8-15, a3=rows r+8 k8-15
            // built above: [0]=st0 rows r, [1]=st0 rows r+8, [2]=st1 rows r, [3]=st1 rows r+8  ✓
#pragma unroll
            for (int vb = 0; vb < 4; vb++) {
                uint32_t va = sb + FKH + 2 * 8192 + swz128(vrow + (uint32_t)ks * 16 * 128 + vb * 32);
                uint32_t rh[4], rl[4];
                ldsm_x4_t(va, rh);
                ldsm_x4_t(va + 8192, rl);
                uint32_t bh0[2] = { rh[0], rh[1] }, bh1[2] = { rh[2], rh[3] };
                uint32_t bl0[2] = { rl[0], rl[1] }, bl1[2] = { rl[2], rl[3] };
                mma16816(o[2 * vb],     aph, bh0);
                mma16816(o[2 * vb],     aph, bl0);
                mma16816(o[2 * vb],     apl, bh0);
                mma16816(o[2 * vb + 1], aph, bh1);
                mma16816(o[2 * vb + 1], aph, bl1);
                mma16816(o[2 * vb + 1], apl, bh1);
            }
        }
    }

    // ---- epilogue: ctx -> bf16 hi/lo at [b*S+s][h*64+dk] ----
    float inv0 = 1.f / l0, inv1 = 1.f / l1;
    int row0 = b * S_ + q0 + w * 16 + (lane >> 2);
    int row1 = row0 + 8;
    int colb = h * 64 + 2 * (lane & 3);
#pragma unroll
    for (int nt = 0; nt < 8; nt++) {
        int col = colb + nt * 8;
        float v0 = o[nt][0] * inv0, v1 = o[nt][1] * inv0;
        float v2 = o[nt][2] * inv1, v3 = o[nt][3] * inv1;
        __nv_bfloat16 hx, hy, lx, ly;
        split1(v0, hx, lx); split1(v1, hy, ly);
        *(uint32_t*)&OutH[(size_t)row0 * D_ + col] = pack2(__bfloat162float(hx), __bfloat162float(hy));
        *(uint32_t*)&OutL[(size_t)row0 * D_ + col] = pack2(__bfloat162float(lx), __bfloat162float(ly));
        split1(v2, hx, lx); split1(v3, hy, ly);
        *(uint32_t*)&OutH[(size_t)row1 * D_ + col] = pack2(__bfloat162float(hx), __bfloat162float(hy));
        *(uint32_t*)&OutL[(size_t)row1 * D_ + col] = pack2(__bfloat162float(lx), __bfloat162float(ly));
    }
}

// ---------------------------------------------------------------------------
extern "C" void kernel_launch(void* const* d_in, const int* in_sizes, int n_in,
                              void* d_out, int out_size)
{
    const float* Q  = (const float*)d_in[0];
    const float* K  = (const float*)d_in[1];
    const float* V  = (const float*)d_in[2];
    // d_in[3] = Mask (guaranteed tril -> hardcoded causal)
    const float* Wq = (const float*)d_in[4];
    const float* bq = (const float*)d_in[5];
    const float* Wk = (const float*)d_in[6];
    const float* bk = (const float*)d_in[7];
    const float* Wv = (const float*)d_in[8];
    const float* bv = (const float*)d_in[9];
    const float* Wo = (const float*)d_in[10];
    const float* bo = (const float*)d_in[11];
    float* out = (float*)d_out;

    __nv_bfloat16 *ah, *al, *wh, *wl, *qh, *ql, *kh, *kl, *vh, *vl;
    cudaGetSymbolAddress((void**)&ah, g_ah);
    cudaGetSymbolAddress((void**)&al, g_al);
    cudaGetSymbolAddress((void**)&wh, g_wh);
    cudaGetSymbolAddress((void**)&wl, g_wl);
    cudaGetSymbolAddress((void**)&qh, g_qh);
    cudaGetSymbolAddress((void**)&ql, g_ql);
    cudaGetSymbolAddress((void**)&kh, g_kh);
    cudaGetSymbolAddress((void**)&kl, g_kl);
    cudaGetSymbolAddress((void**)&vh, g_vh);
    cudaGetSymbolAddress((void**)&vl, g_vl);

    cudaFuncSetAttribute(flash_mma, cudaFuncAttributeMaxDynamicSharedMemorySize, FSM_TOTAL);

    const int nA = M_ * D_;
    const int nW = D_ * D_;
    dim3 gemmGrid(D_ / 128, M_ / 128);   // (8, 32)

    split_bf16<<<nA / 1024, 256>>>(Q, ah, al, nA);
    split_bf16<<<nW / 1024, 256>>>(Wq, wh, wl, nW);
    mma_gemm<<<gemmGrid, 256>>>(ah, al, wh, wl, bq, qh, ql, nullptr, 1);

    split_bf16<<<nA / 1024, 256>>>(K, ah, al, nA);
    split_bf16<<<nW / 1024, 256>>>(Wk, wh, wl, nW);
    mma_gemm<<<gemmGrid, 256>>>(ah, al, wh, wl, bk, kh, kl, nullptr, 1);

    split_bf16<<<nA / 1024, 256>>>(V, ah, al, nA);
    split_bf16<<<nW / 1024, 256>>>(Wv, wh, wl, nW);
    mma_gemm<<<gemmGrid, 256>>>(ah, al, wh, wl, bv, vh, vl, nullptr, 1);

    dim3 attnGrid(S_ / 128, H_, B_);     // (16, 16, 2)
    flash_mma<<<attnGrid, 256, FSM_TOTAL>>>(qh, ql, kh, kl, vh, vl, ah, al);

    split_bf16<<<nW / 1024, 256>>>(Wo, wh, wl, nW);
    mma_gemm<<<gemmGrid, 256>>>(ah, al, wh, wl, bo, nullptr, nullptr, out, 0);
}

// round 5
// speedup vs baseline: 3.5565x; 1.0712x over previous
#include <cuda_runtime.h>
#include <cuda_bf16.h>
#include <math.h>
#include <stdint.h>

#define B_  2
#define S_  2048
#define D_  1024
#define H_  16
#define DK_ 64
#define M_  (B_ * S_)                 // 4096
#define NA_ (M_ * D_)                 // 4194304 (one activation)
#define NW_ (D_ * D_)                 // 1048576 (one weight)
#define BHS_ (B_ * H_ * S_ * DK_)     // 4194304 (one head-layout tensor)

// ---------------------------------------------------------------------------
// Scratch (allocation-free rule: __device__ globals)
// ---------------------------------------------------------------------------
__device__ __nv_bfloat16 g_ah[3 * NA_];   // activation hi: slots 0..2 (Q,K,V in / ctx slot 0)
__device__ __nv_bfloat16 g_al[3 * NA_];
__device__ __nv_bfloat16 g_wh[4 * NW_];   // weights hi: Wq,Wk,Wv,Wo
__device__ __nv_bfloat16 g_wl[4 * NW_];
__device__ __nv_bfloat16 g_qkvh[3 * BHS_]; // q,k,v head-layout hi
__device__ __nv_bfloat16 g_qkvl[3 * BHS_];

struct Bias3 { const float* b0; const float* b1; const float* b2; };
struct In3   { const float* x0; const float* x1; const float* x2; };
struct In4   { const float* x0; const float* x1; const float* x2; const float* x3; };

// ---------------------------------------------------------------------------
// helpers (portable sm_80+ ISA: ldmatrix + mma.sync + cp.async)
// ---------------------------------------------------------------------------
__device__ __forceinline__ uint32_t smem_u32(const void* p) {
    uint32_t a;
    asm("{ .reg .u64 t; cvta.to.shared.u64 t, %1; cvt.u32.u64 %0, t; }"
        : "=r"(a) : "l"(p));
    return a;
}
__device__ __forceinline__ void ldsm_x4(uint32_t addr, uint32_t* r) {
    asm volatile("ldmatrix.sync.aligned.m8n8.x4.shared.b16 {%0,%1,%2,%3}, [%4];"
        : "=r"(r[0]), "=r"(r[1]), "=r"(r[2]), "=r"(r[3]) : "r"(addr));
}
__device__ __forceinline__ void ldsm_x4_t(uint32_t addr, uint32_t* r) {
    asm volatile("ldmatrix.sync.aligned.m8n8.x4.trans.shared.b16 {%0,%1,%2,%3}, [%4];"
        : "=r"(r[0]), "=r"(r[1]), "=r"(r[2]), "=r"(r[3]) : "r"(addr));
}
__device__ __forceinline__ void mma16816(float* d, const uint32_t* a, const uint32_t* b) {
    asm volatile("mma.sync.aligned.m16n8k16.row.col.f32.bf16.bf16.f32 "
        "{%0,%1,%2,%3}, {%4,%5,%6,%7}, {%8,%9}, {%0,%1,%2,%3};"
        : "+f"(d[0]), "+f"(d[1]), "+f"(d[2]), "+f"(d[3])
        : "r"(a[0]), "r"(a[1]), "r"(a[2]), "r"(a[3]), "r"(b[0]), "r"(b[1]));
}
__device__ __forceinline__ void cp16(uint32_t d, const void* g) {
    asm volatile("cp.async.cg.shared.global [%0], [%1], 16;" :: "r"(d), "l"(g));
}
#define CP_COMMIT() asm volatile("cp.async.commit_group;")
#define CP_WAIT0()  asm volatile("cp.async.wait_group 0;")

__device__ __forceinline__ uint32_t swz64(uint32_t b)  { return b ^ ((b >> 3) & 0x30); }
__device__ __forceinline__ uint32_t swz128(uint32_t b) { return b ^ ((b >> 3) & 0x70); }
__device__ __forceinline__ void split1(float v, __nv_bfloat16& h, __nv_bfloat16& l) {
    h = __float2bfloat16(v);
    l = __float2bfloat16(v - __bfloat162float(h));
}

// ---------------------------------------------------------------------------
// fused splits
// ---------------------------------------------------------------------------
__global__ __launch_bounds__(256) void split_qkv(In3 in, __nv_bfloat16* __restrict__ hi,
                                                 __nv_bfloat16* __restrict__ lo)
{
    int z = blockIdx.y;
    const float* x = (z == 0) ? in.x0 : (z == 1) ? in.x1 : in.x2;
    size_t off = (size_t)z * NA_;
    int i = (blockIdx.x * 256 + threadIdx.x) * 4;
    float4 v = *(const float4*)(x + i);
    __nv_bfloat16 h0, h1, h2, h3, l0, l1, l2, l3;
    split1(v.x, h0, l0); split1(v.y, h1, l1);
    split1(v.z, h2, l2); split1(v.w, h3, l3);
    __nv_bfloat162* hp = (__nv_bfloat162*)(hi + off + i);
    __nv_bfloat162* lp = (__nv_bfloat162*)(lo + off + i);
    hp[0] = __nv_bfloat162(h0, h1); hp[1] = __nv_bfloat162(h2, h3);
    lp[0] = __nv_bfloat162(l0, l1); lp[1] = __nv_bfloat162(l2, l3);
}

__global__ __launch_bounds__(256) void split_w(In4 in, __nv_bfloat16* __restrict__ hi,
                                               __nv_bfloat16* __restrict__ lo)
{
    int z = blockIdx.y;
    const float* x = (z == 0) ? in.x0 : (z == 1) ? in.x1 : (z == 2) ? in.x2 : in.x3;
    size_t off = (size_t)z * NW_;
    int i = (blockIdx.x * 256 + threadIdx.x) * 4;
    float4 v = *(const float4*)(x + i);
    __nv_bfloat16 h0, h1, h2, h3, l0, l1, l2, l3;
    split1(v.x, h0, l0); split1(v.y, h1, l1);
    split1(v.z, h2, l2); split1(v.w, h3, l3);
    __nv_bfloat162* hp = (__nv_bfloat162*)(hi + off + i);
    __nv_bfloat162* lp = (__nv_bfloat162*)(lo + off + i);
    hp[0] = __nv_bfloat162(h0, h1); hp[1] = __nv_bfloat162(h2, h3);
    lp[0] = __nv_bfloat162(l0, l1); lp[1] = __nv_bfloat162(l2, l3);
}

// ---------------------------------------------------------------------------
// Tensor-core GEMM (split bf16, cp.async 2-stage pipeline, batched over z):
//   C[m][n] = sum_k A[m][k]*W[n][k] + bias[n]
// CTA 128x128, 8 warps (2m x 4n), warp tile 64x32, BK=32, SW64 smem swizzle.
// mode=1: bf16 hi/lo out at [B,H,S,DK] (offset z*strideC); 0: fp32 flat.
// ---------------------------------------------------------------------------
#define GSM_STAGE 32768           // 4 tiles x 8192
#define GSM_TOTAL 65536           // 2 stages

__global__ __launch_bounds__(256) void mma_gemm(
    const __nv_bfloat16* __restrict__ Ah, const __nv_bfloat16* __restrict__ Al,
    size_t strideA,
    const __nv_bfloat16* __restrict__ Wh, const __nv_bfloat16* __restrict__ Wl,
    size_t strideW, Bias3 bs,
    __nv_bfloat16* __restrict__ Chi, __nv_bfloat16* __restrict__ Clo, size_t strideC,
    float* __restrict__ Cf, int mode)
{
    extern __shared__ char sm[];
    const uint32_t sb = smem_u32(sm);
    const int tid = threadIdx.x;
    const int lane = tid & 31;
    const int wid = tid >> 5;
    const int z = blockIdx.z;
    const int bm = blockIdx.y * 128;
    const int bn = blockIdx.x * 128;
    const int wm = (wid & 1) * 64;
    const int wn = (wid >> 1) * 32;

    const float* bias = (z == 0) ? bs.b0 : (z == 1) ? bs.b1 : bs.b2;
    Ah += (size_t)z * strideA; Al += (size_t)z * strideA;
    Wh += (size_t)z * strideW; Wl += (size_t)z * strideW;

    float acc[4][4][4];
#pragma unroll
    for (int mt = 0; mt < 4; mt++)
#pragma unroll
        for (int nt = 0; nt < 4; nt++)
#pragma unroll
            for (int r = 0; r < 4; r++) acc[mt][nt][r] = 0.f;

    const int g = lane >> 3, r8 = lane & 7;
    uint32_t rowA[4], rowB[2];
#pragma unroll
    for (int mt = 0; mt < 4; mt++)
        rowA[mt] = (uint32_t)(wm + mt * 16 + (g & 1) * 8 + r8) * 64;
#pragma unroll
    for (int np = 0; np < 2; np++)
        rowB[np] = (uint32_t)(wn + np * 16 + (g >> 1) * 8 + r8) * 64;
    const uint32_t chA = (uint32_t)(g >> 1) * 16;
    const uint32_t chB = (uint32_t)(g & 1) * 16;

    const int gl_row0 = tid >> 2, gl_c0 = tid & 3;
    const int gl_row1 = (tid + 256) >> 2, gl_c1 = tid & 3;
    const uint32_t st0 = swz64((uint32_t)gl_row0 * 64 + gl_c0 * 16);
    const uint32_t st1 = swz64((uint32_t)gl_row1 * 64 + gl_c1 * 16);

    const __nv_bfloat16* srcs[4] = { Ah, Al, Wh, Wl };
    const int rbase[4] = { bm, bm, bn, bn };

    // prologue: stage 0
#pragma unroll
    for (int t = 0; t < 4; t++) {
        const __nv_bfloat16* s = srcs[t];
        cp16(sb + t * 8192 + st0, s + (size_t)(rbase[t] + gl_row0) * D_ + gl_c0 * 8);
        cp16(sb + t * 8192 + st1, s + (size_t)(rbase[t] + gl_row1) * D_ + gl_c1 * 8);
    }
    CP_COMMIT();

    for (int kt = 0; kt < 32; kt++) {
        const uint32_t stb = sb + (uint32_t)(kt & 1) * GSM_STAGE;
        CP_WAIT0();
        __syncthreads();

        if (kt + 1 < 32) {
            const int k0 = (kt + 1) * 32;
            const uint32_t nstb = sb + (uint32_t)((kt + 1) & 1) * GSM_STAGE;
#pragma unroll
            for (int t = 0; t < 4; t++) {
                const __nv_bfloat16* s = srcs[t];
                cp16(nstb + t * 8192 + st0, s + (size_t)(rbase[t] + gl_row0) * D_ + k0 + gl_c0 * 8);
                cp16(nstb + t * 8192 + st1, s + (size_t)(rbase[t] + gl_row1) * D_ + k0 + gl_c1 * 8);
            }
            CP_COMMIT();
        }

#pragma unroll
        for (int ks = 0; ks < 2; ks++) {
            const uint32_t kb = (uint32_t)ks * 32;
            uint32_t ah[4][4], al[4][4], bh[4][2], bl[4][2];
#pragma unroll
            for (int mt = 0; mt < 4; mt++) {
                uint32_t a = stb + swz64(rowA[mt] + kb + chA);
                ldsm_x4(a, ah[mt]);
                ldsm_x4(a + 8192, al[mt]);
            }
#pragma unroll
            for (int np = 0; np < 2; np++) {
                uint32_t a = stb + 2 * 8192 + swz64(rowB[np] + kb + chB);
                uint32_t q[4];
                ldsm_x4(a, q);
                bh[2 * np][0] = q[0]; bh[2 * np][1] = q[1];
                bh[2 * np + 1][0] = q[2]; bh[2 * np + 1][1] = q[3];
                ldsm_x4(a + 8192, q);
                bl[2 * np][0] = q[0]; bl[2 * np][1] = q[1];
                bl[2 * np + 1][0] = q[2]; bl[2 * np + 1][1] = q[3];
            }
#pragma unroll
            for (int mt = 0; mt < 4; mt++)
#pragma unroll
                for (int nt = 0; nt < 4; nt++) {
                    mma16816(acc[mt][nt], ah[mt], bh[nt]);
                    mma16816(acc[mt][nt], ah[mt], bl[nt]);
                    mma16816(acc[mt][nt], al[mt], bh[nt]);
                }
        }
    }

    const int fr = lane >> 2;
    const int fc = (lane & 3) * 2;
    Chi += (size_t)z * strideC; Clo += (size_t)z * strideC;
#pragma unroll
    for (int mt = 0; mt < 4; mt++) {
#pragma unroll
        for (int nt = 0; nt < 4; nt++) {
            int col = bn + wn + nt * 8 + fc;
            float bx = bias[col], by = bias[col + 1];
#pragma unroll
            for (int half = 0; half < 2; half++) {
                int row = bm + wm + mt * 16 + fr + half * 8;
                float vx = acc[mt][nt][2 * half] + bx;
                float vy = acc[mt][nt][2 * half + 1] + by;
                if (mode) {
                    int b = row >> 11, s = row & (S_ - 1);
                    int h = col >> 6, dk = col & 63;
                    size_t o = (((size_t)b * H_ + h) * S_ + s) * DK_ + dk;
                    __nv_bfloat16 hx, hy, lx, ly;
                    split1(vx, hx, lx); split1(vy, hy, ly);
                    *(__nv_bfloat162*)&Chi[o] = __nv_bfloat162(hx, hy);
                    *(__nv_bfloat162*)&Clo[o] = __nv_bfloat162(lx, ly);
                } else {
                    *(float2*)&Cf[(size_t)row * D_ + col] = make_float2(vx, vy);
                }
            }
        }
    }
}

// ---------------------------------------------------------------------------
// Flash attention on mma.sync, split bf16, fp32 accum, causal, unscaled.
// CTA = 128 q-rows of one (b,h); q-tile order reversed so long CTAs start first.
// ---------------------------------------------------------------------------
#define FQH 0
#define FQL 16384
#define FKH 32768
#define FSM_TOTAL 65536

__global__ __launch_bounds__(256, 2) void flash_mma(
    const __nv_bfloat16* __restrict__ Qh, const __nv_bfloat16* __restrict__ Ql,
    const __nv_bfloat16* __restrict__ Kh, const __nv_bfloat16* __restrict__ Kl,
    const __nv_bfloat16* __restrict__ Vh, const __nv_bfloat16* __restrict__ Vl,
    __nv_bfloat16* __restrict__ OutH, __nv_bfloat16* __restrict__ OutL)
{
    extern __shared__ char fsm[];
    const uint32_t sb = smem_u32(fsm);
    const int tid = threadIdx.x;
    const int lane = tid & 31;
    const int w = tid >> 5;
    const int qt = gridDim.x - 1 - blockIdx.x;     // big tiles scheduled first
    const int h = blockIdx.y, b = blockIdx.z;
    const size_t base = ((size_t)b * H_ + h) * S_ * DK_;
    const int q0 = qt * 128;

#pragma unroll
    for (int i = 0; i < 4; i++) {
        int idx = i * 256 + tid;
        int row = idx >> 3, ch = idx & 7;
        uint4 vh_ = *(const uint4*)(Qh + base + (size_t)(q0 + row) * DK_ + ch * 8);
        uint4 vl_ = *(const uint4*)(Ql + base + (size_t)(q0 + row) * DK_ + ch * 8);
        uint32_t sw = swz128((uint32_t)row * 128 + ch * 16);
        *(uint4*)(fsm + FQH + sw) = vh_;
        *(uint4*)(fsm + FQL + sw) = vl_;
    }

    float o[8][4];
#pragma unroll
    for (int nt = 0; nt < 8; nt++)
#pragma unroll
        for (int r = 0; r < 4; r++) o[nt][r] = 0.f;
    float m0 = -INFINITY, m1 = -INFINITY, l0 = 0.f, l1 = 0.f;

    const int g = lane >> 3, r8 = lane & 7;
    const uint32_t qrow = (uint32_t)(w * 16 + (g & 1) * 8 + r8) * 128 + (uint32_t)(g >> 1) * 16;
    const uint32_t krow = (uint32_t)((g >> 1) * 8 + r8) * 128 + (uint32_t)(g & 1) * 16;
    const uint32_t vrow = (uint32_t)((lane & 7) + ((lane >> 3) & 1) * 8) * 128
                        + (uint32_t)(lane >> 4) * 16;

    const int nkt = 2 * qt + 2;
    const int wq = q0 + w * 16;

    for (int kt = 0; kt < nkt; kt++) {
        const int k0 = kt * 64;
        __syncthreads();
#pragma unroll
        for (int t = 0; t < 4; t++) {      // 0=Kh 1=Kl 2=Vh 3=Vl
            const __nv_bfloat16* s2 = (t == 0) ? Kh : (t == 1) ? Kl : (t == 2) ? Vh : Vl;
#pragma unroll
            for (int half = 0; half < 2; half++) {
                int ci = half * 256 + tid;
                int row = ci >> 3, ch = ci & 7;
                uint4 val = *(const uint4*)(s2 + base + (size_t)(k0 + row) * DK_ + ch * 8);
                *(uint4*)(fsm + FKH + t * 8192 + swz128((uint32_t)row * 128 + ch * 16)) = val;
            }
        }
        __syncthreads();

        float s[8][4];
#pragma unroll
        for (int nt = 0; nt < 8; nt++)
#pragma unroll
            for (int r = 0; r < 4; r++) s[nt][r] = 0.f;

#pragma unroll
        for (int ks = 0; ks < 4; ks++) {
            uint32_t qh_f[4], ql_f[4];
            uint32_t qa = sb + FQH + swz128(qrow + ks * 32);
            ldsm_x4(qa, qh_f);
            ldsm_x4(qa + (FQL - FQH), ql_f);
#pragma unroll
            for (int np = 0; np < 4; np++) {
                uint32_t ka = sb + FKH + swz128(krow + (uint32_t)np * 16 * 128 + ks * 32);
                uint32_t rh[4], rl[4];
                ldsm_x4(ka, rh);
                ldsm_x4(ka + 8192, rl);
                uint32_t bh0[2] = { rh[0], rh[1] }, bh1[2] = { rh[2], rh[3] };
                uint32_t bl0[2] = { rl[0], rl[1] }, bl1[2] = { rl[2], rl[3] };
                mma16816(s[2 * np],     qh_f, bh0);
                mma16816(s[2 * np],     qh_f, bl0);
                mma16816(s[2 * np],     ql_f, bh0);
                mma16816(s[2 * np + 1], qh_f, bh1);
                mma16816(s[2 * np + 1], qh_f, bl1);
                mma16816(s[2 * np + 1], ql_f, bh1);
            }
        }

        if (k0 + 63 > wq) {
            int r0g = wq + (lane >> 2), r1g = r0g + 8;
            int cb = k0 + 2 * (lane & 3);
#pragma unroll
            for (int nt = 0; nt < 8; nt++) {
                int key = cb + nt * 8;
                if (key     > r0g) s[nt][0] = -1e9f;
                if (key + 1 > r0g) s[nt][1] = -1e9f;
                if (key     > r1g) s[nt][2] = -1e9f;
                if (key + 1 > r1g) s[nt][3] = -1e9f;
            }
        }

        float rm0 = -INFINITY, rm1 = -INFINITY;
#pragma unroll
        for (int nt = 0; nt < 8; nt++) {
            rm0 = fmaxf(rm0, fmaxf(s[nt][0], s[nt][1]));
            rm1 = fmaxf(rm1, fmaxf(s[nt][2], s[nt][3]));
        }
        rm0 = fmaxf(rm0, __shfl_xor_sync(0xffffffffu, rm0, 1));
        rm0 = fmaxf(rm0, __shfl_xor_sync(0xffffffffu, rm0, 2));
        rm1 = fmaxf(rm1, __shfl_xor_sync(0xffffffffu, rm1, 1));
        rm1 = fmaxf(rm1, __shfl_xor_sync(0xffffffffu, rm1, 2));
        float mn0 = fmaxf(m0, rm0), mn1 = fmaxf(m1, rm1);
        float sc0 = __expf(m0 - mn0), sc1 = __expf(m1 - mn1);
        float rs0 = 0.f, rs1 = 0.f;
#pragma unroll
        for (int nt = 0; nt < 8; nt++) {
            s[nt][0] = __expf(s[nt][0] - mn0);
            s[nt][1] = __expf(s[nt][1] - mn0);
            s[nt][2] = __expf(s[nt][2] - mn1);
            s[nt][3] = __expf(s[nt][3] - mn1);
            rs0 += s[nt][0] + s[nt][1];
            rs1 += s[nt][2] + s[nt][3];
        }
        rs0 += __shfl_xor_sync(0xffffffffu, rs0, 1);
        rs0 += __shfl_xor_sync(0xffffffffu, rs0, 2);
        rs1 += __shfl_xor_sync(0xffffffffu, rs1, 1);
        rs1 += __shfl_xor_sync(0xffffffffu, rs1, 2);
        l0 = l0 * sc0 + rs0; m0 = mn0;
        l1 = l1 * sc1 + rs1; m1 = mn1;
#pragma unroll
        for (int nt = 0; nt < 8; nt++) {
            o[nt][0] *= sc0; o[nt][1] *= sc0;
            o[nt][2] *= sc1; o[nt][3] *= sc1;
        }

#pragma unroll
        for (int ks = 0; ks < 4; ks++) {
            uint32_t aph[4], apl[4];
#pragma unroll
            for (int half = 0; half < 2; half++) {
                int st = 2 * ks + half;
                __nv_bfloat16 h0_, l0_, h1_, l1_, h2_, l2_, h3_, l3_;
                split1(s[st][0], h0_, l0_); split1(s[st][1], h1_, l1_);
                split1(s[st][2], h2_, l2_); split1(s[st][3], h3_, l3_);
                __nv_bfloat162 ph01(h0_, h1_), pl01(l0_, l1_);
                __nv_bfloat162 ph23(h2_, h3_), pl23(l2_, l3_);
                aph[2 * half]     = *(uint32_t*)&ph01;
                aph[2 * half + 1] = *(uint32_t*)&ph23;
                apl[2 * half]     = *(uint32_t*)&pl01;
                apl[2 * half + 1] = *(uint32_t*)&pl23;
            }
#pragma unroll
            for (int vb = 0; vb < 4; vb++) {
                uint32_t va = sb + FKH + 2 * 8192 + swz128(vrow + (uint32_t)ks * 16 * 128 + vb * 32);
                uint32_t rh[4], rl[4];
                ldsm_x4_t(va, rh);
                ldsm_x4_t(va + 8192, rl);
                uint32_t bh0[2] = { rh[0], rh[1] }, bh1[2] = { rh[2], rh[3] };
                uint32_t bl0[2] = { rl[0], rl[1] }, bl1[2] = { rl[2], rl[3] };
                mma16816(o[2 * vb],     aph, bh0);
                mma16816(o[2 * vb],     aph, bl0);
                mma16816(o[2 * vb],     apl, bh0);
                mma16816(o[2 * vb + 1], aph, bh1);
                mma16816(o[2 * vb + 1], aph, bl1);
                mma16816(o[2 * vb + 1], apl, bh1);
            }
        }
    }

    float inv0 = 1.f / l0, inv1 = 1.f / l1;
    int row0 = b * S_ + q0 + w * 16 + (lane >> 2);
    int row1 = row0 + 8;
    int colb = h * 64 + 2 * (lane & 3);
#pragma unroll
    for (int nt = 0; nt < 8; nt++) {
        int col = colb + nt * 8;
        float v0 = o[nt][0] * inv0, v1 = o[nt][1] * inv0;
        float v2 = o[nt][2] * inv1, v3 = o[nt][3] * inv1;
        __nv_bfloat16 hx, hy, lx, ly;
        split1(v0, hx, lx); split1(v1, hy, ly);
        *(__nv_bfloat162*)&OutH[(size_t)row0 * D_ + col] = __nv_bfloat162(hx, hy);
        *(__nv_bfloat162*)&OutL[(size_t)row0 * D_ + col] = __nv_bfloat162(lx, ly);
        split1(v2, hx, lx); split1(v3, hy, ly);
        *(__nv_bfloat162*)&OutH[(size_t)row1 * D_ + col] = __nv_bfloat162(hx, hy);
        *(__nv_bfloat162*)&OutL[(size_t)row1 * D_ + col] = __nv_bfloat162(lx, ly);
    }
}

// ---------------------------------------------------------------------------
extern "C" void kernel_launch(void* const* d_in, const int* in_sizes, int n_in,
                              void* d_out, int out_size)
{
    const float* Q  = (const float*)d_in[0];
    const float* K  = (const float*)d_in[1];
    const float* V  = (const float*)d_in[2];
    // d_in[3] = Mask (guaranteed tril -> hardcoded causal)
    const float* Wq = (const float*)d_in[4];
    const float* bq = (const float*)d_in[5];
    const float* Wk = (const float*)d_in[6];
    const float* bk = (const float*)d_in[7];
    const float* Wv = (const float*)d_in[8];
    const float* bv = (const float*)d_in[9];
    const float* Wo = (const float*)d_in[10];
    const float* bo = (const float*)d_in[11];
    float* out = (float*)d_out;

    __nv_bfloat16 *ah, *al, *wh, *wl, *qkvh, *qkvl;
    cudaGetSymbolAddress((void**)&ah, g_ah);
    cudaGetSymbolAddress((void**)&al, g_al);
    cudaGetSymbolAddress((void**)&wh, g_wh);
    cudaGetSymbolAddress((void**)&wl, g_wl);
    cudaGetSymbolAddress((void**)&qkvh, g_qkvh);
    cudaGetSymbolAddress((void**)&qkvl, g_qkvl);

    static bool attr_done = false;
    if (!attr_done) {
        cudaFuncSetAttribute(mma_gemm, cudaFuncAttributeMaxDynamicSharedMemorySize, GSM_TOTAL);
        cudaFuncSetAttribute(flash_mma, cudaFuncAttributeMaxDynamicSharedMemorySize, FSM_TOTAL);
        attr_done = true;
    }

    // splits: all weights (4) and Q,K,V (3)
    In4 ws = { Wq, Wk, Wv, Wo };
    split_w<<<dim3(NW_ / 1024, 4), 256>>>(ws, wh, wl);
    In3 xs = { Q, K, V };
    split_qkv<<<dim3(NA_ / 1024, 3), 256>>>(xs, ah, al);

    // batched QKV projection (z = 0,1,2)
    Bias3 bqkv = { bq, bk, bv };
    mma_gemm<<<dim3(D_ / 128, M_ / 128, 3), 256, GSM_TOTAL>>>(
        ah, al, NA_, wh, wl, NW_, bqkv, qkvh, qkvl, BHS_, nullptr, 1);

    // attention (writes ctx hi/lo into g_ah/g_al slot 0)
    flash_mma<<<dim3(S_ / 128, H_, B_), 256, FSM_TOTAL>>>(
        qkvh, qkvl, qkvh + BHS_, qkvl + BHS_, qkvh + 2 * BHS_, qkvl + 2 * BHS_, ah, al);

    // output projection (weight slot 3)
    Bias3 bout = { bo, bo, bo };
    mma_gemm<<<dim3(D_ / 128, M_ / 128, 1), 256, GSM_TOTAL>>>(
        ah, al, 0, wh + 3 * (size_t)NW_, wl + 3 * (size_t)NW_, 0, bout,
        nullptr, nullptr, 0, out, 0);
}

// round 6
// speedup vs baseline: 3.8063x; 1.0703x over previous
#include <cuda_runtime.h>
#include <cuda_bf16.h>
#include <math.h>
#include <stdint.h>

#define B_  2
#define S_  2048
#define D_  1024
#define H_  16
#define DK_ 64
#define M_  (B_ * S_)                 // 4096
#define NA_ (M_ * D_)                 // 4194304
#define NW_ (D_ * D_)                 // 1048576
#define BHS_ (B_ * H_ * S_ * DK_)     // 4194304

// ---------------------------------------------------------------------------
// Scratch (allocation-free rule: __device__ globals)
// ---------------------------------------------------------------------------
__device__ __nv_bfloat16 g_ah[3 * NA_];
__device__ __nv_bfloat16 g_al[3 * NA_];
__device__ __nv_bfloat16 g_wh[4 * NW_];
__device__ __nv_bfloat16 g_wl[4 * NW_];
__device__ __nv_bfloat16 g_qkvh[3 * BHS_];
__device__ __nv_bfloat16 g_qkvl[3 * BHS_];

struct Bias3 { const float* b0; const float* b1; const float* b2; };
struct In3   { const float* x0; const float* x1; const float* x2; };
struct In4   { const float* x0; const float* x1; const float* x2; const float* x3; };

// ---------------------------------------------------------------------------
// helpers
// ---------------------------------------------------------------------------
__device__ __forceinline__ uint32_t smem_u32(const void* p) {
    uint32_t a;
    asm("{ .reg .u64 t; cvta.to.shared.u64 t, %1; cvt.u32.u64 %0, t; }"
        : "=r"(a) : "l"(p));
    return a;
}
__device__ __forceinline__ void ldsm_x4(uint32_t addr, uint32_t* r) {
    asm volatile("ldmatrix.sync.aligned.m8n8.x4.shared.b16 {%0,%1,%2,%3}, [%4];"
        : "=r"(r[0]), "=r"(r[1]), "=r"(r[2]), "=r"(r[3]) : "r"(addr));
}
__device__ __forceinline__ void ldsm_x4_t(uint32_t addr, uint32_t* r) {
    asm volatile("ldmatrix.sync.aligned.m8n8.x4.trans.shared.b16 {%0,%1,%2,%3}, [%4];"
        : "=r"(r[0]), "=r"(r[1]), "=r"(r[2]), "=r"(r[3]) : "r"(addr));
}
__device__ __forceinline__ void mma16816(float* d, const uint32_t* a, const uint32_t* b) {
    asm volatile("mma.sync.aligned.m16n8k16.row.col.f32.bf16.bf16.f32 "
        "{%0,%1,%2,%3}, {%4,%5,%6,%7}, {%8,%9}, {%0,%1,%2,%3};"
        : "+f"(d[0]), "+f"(d[1]), "+f"(d[2]), "+f"(d[3])
        : "r"(a[0]), "r"(a[1]), "r"(a[2]), "r"(a[3]), "r"(b[0]), "r"(b[1]));
}
__device__ __forceinline__ void cp16(uint32_t d, const void* g) {
    asm volatile("cp.async.cg.shared.global [%0], [%1], 16;" :: "r"(d), "l"(g));
}
#define CP_COMMIT() asm volatile("cp.async.commit_group;")
#define CP_WAIT0()  asm volatile("cp.async.wait_group 0;")

__device__ __forceinline__ uint32_t swz64(uint32_t b)  { return b ^ ((b >> 3) & 0x30); }
__device__ __forceinline__ uint32_t swz128(uint32_t b) { return b ^ ((b >> 3) & 0x70); }
__device__ __forceinline__ void split1(float v, __nv_bfloat16& h, __nv_bfloat16& l) {
    h = __float2bfloat16(v);
    l = __float2bfloat16(v - __bfloat162float(h));
}

// ---------------------------------------------------------------------------
// fused splits
// ---------------------------------------------------------------------------
__global__ __launch_bounds__(256) void split_qkv(In3 in, __nv_bfloat16* __restrict__ hi,
                                                 __nv_bfloat16* __restrict__ lo)
{
    int z = blockIdx.y;
    const float* x = (z == 0) ? in.x0 : (z == 1) ? in.x1 : in.x2;
    size_t off = (size_t)z * NA_;
    int i = (blockIdx.x * 256 + threadIdx.x) * 4;
    float4 v = *(const float4*)(x + i);
    __nv_bfloat16 h0, h1, h2, h3, l0, l1, l2, l3;
    split1(v.x, h0, l0); split1(v.y, h1, l1);
    split1(v.z, h2, l2); split1(v.w, h3, l3);
    __nv_bfloat162* hp = (__nv_bfloat162*)(hi + off + i);
    __nv_bfloat162* lp = (__nv_bfloat162*)(lo + off + i);
    hp[0] = __nv_bfloat162(h0, h1); hp[1] = __nv_bfloat162(h2, h3);
    lp[0] = __nv_bfloat162(l0, l1); lp[1] = __nv_bfloat162(l2, l3);
}

__global__ __launch_bounds__(256) void split_w(In4 in, __nv_bfloat16* __restrict__ hi,
                                               __nv_bfloat16* __restrict__ lo)
{
    int z = blockIdx.y;
    const float* x = (z == 0) ? in.x0 : (z == 1) ? in.x1 : (z == 2) ? in.x2 : in.x3;
    size_t off = (size_t)z * NW_;
    int i = (blockIdx.x * 256 + threadIdx.x) * 4;
    float4 v = *(const float4*)(x + i);
    __nv_bfloat16 h0, h1, h2, h3, l0, l1, l2, l3;
    split1(v.x, h0, l0); split1(v.y, h1, l1);
    split1(v.z, h2, l2); split1(v.w, h3, l3);
    __nv_bfloat162* hp = (__nv_bfloat162*)(hi + off + i);
    __nv_bfloat162* lp = (__nv_bfloat162*)(lo + off + i);
    hp[0] = __nv_bfloat162(h0, h1); hp[1] = __nv_bfloat162(h2, h3);
    lp[0] = __nv_bfloat162(l0, l1); lp[1] = __nv_bfloat162(l2, l3);
}

// ---------------------------------------------------------------------------
// Tensor-core GEMM (split bf16, cp.async 2-stage, batched over z) — as R5
// ---------------------------------------------------------------------------
#define GSM_STAGE 32768
#define GSM_TOTAL 65536

__global__ __launch_bounds__(256) void mma_gemm(
    const __nv_bfloat16* __restrict__ Ah, const __nv_bfloat16* __restrict__ Al,
    size_t strideA,
    const __nv_bfloat16* __restrict__ Wh, const __nv_bfloat16* __restrict__ Wl,
    size_t strideW, Bias3 bs,
    __nv_bfloat16* __restrict__ Chi, __nv_bfloat16* __restrict__ Clo, size_t strideC,
    float* __restrict__ Cf, int mode)
{
    extern __shared__ char sm[];
    const uint32_t sb = smem_u32(sm);
    const int tid = threadIdx.x;
    const int lane = tid & 31;
    const int wid = tid >> 5;
    const int z = blockIdx.z;
    const int bm = blockIdx.y * 128;
    const int bn = blockIdx.x * 128;
    const int wm = (wid & 1) * 64;
    const int wn = (wid >> 1) * 32;

    const float* bias = (z == 0) ? bs.b0 : (z == 1) ? bs.b1 : bs.b2;
    Ah += (size_t)z * strideA; Al += (size_t)z * strideA;
    Wh += (size_t)z * strideW; Wl += (size_t)z * strideW;

    float acc[4][4][4];
#pragma unroll
    for (int mt = 0; mt < 4; mt++)
#pragma unroll
        for (int nt = 0; nt < 4; nt++)
#pragma unroll
            for (int r = 0; r < 4; r++) acc[mt][nt][r] = 0.f;

    const int g = lane >> 3, r8 = lane & 7;
    uint32_t rowA[4], rowB[2];
#pragma unroll
    for (int mt = 0; mt < 4; mt++)
        rowA[mt] = (uint32_t)(wm + mt * 16 + (g & 1) * 8 + r8) * 64;
#pragma unroll
    for (int np = 0; np < 2; np++)
        rowB[np] = (uint32_t)(wn + np * 16 + (g >> 1) * 8 + r8) * 64;
    const uint32_t chA = (uint32_t)(g >> 1) * 16;
    const uint32_t chB = (uint32_t)(g & 1) * 16;

    const int gl_row0 = tid >> 2, gl_c0 = tid & 3;
    const int gl_row1 = (tid + 256) >> 2, gl_c1 = tid & 3;
    const uint32_t st0 = swz64((uint32_t)gl_row0 * 64 + gl_c0 * 16);
    const uint32_t st1 = swz64((uint32_t)gl_row1 * 64 + gl_c1 * 16);

    const __nv_bfloat16* srcs[4] = { Ah, Al, Wh, Wl };
    const int rbase[4] = { bm, bm, bn, bn };

#pragma unroll
    for (int t = 0; t < 4; t++) {
        const __nv_bfloat16* s = srcs[t];
        cp16(sb + t * 8192 + st0, s + (size_t)(rbase[t] + gl_row0) * D_ + gl_c0 * 8);
        cp16(sb + t * 8192 + st1, s + (size_t)(rbase[t] + gl_row1) * D_ + gl_c1 * 8);
    }
    CP_COMMIT();

    for (int kt = 0; kt < 32; kt++) {
        const uint32_t stb = sb + (uint32_t)(kt & 1) * GSM_STAGE;
        CP_WAIT0();
        __syncthreads();

        if (kt + 1 < 32) {
            const int k0 = (kt + 1) * 32;
            const uint32_t nstb = sb + (uint32_t)((kt + 1) & 1) * GSM_STAGE;
#pragma unroll
            for (int t = 0; t < 4; t++) {
                const __nv_bfloat16* s = srcs[t];
                cp16(nstb + t * 8192 + st0, s + (size_t)(rbase[t] + gl_row0) * D_ + k0 + gl_c0 * 8);
                cp16(nstb + t * 8192 + st1, s + (size_t)(rbase[t] + gl_row1) * D_ + k0 + gl_c1 * 8);
            }
            CP_COMMIT();
        }

#pragma unroll
        for (int ks = 0; ks < 2; ks++) {
            const uint32_t kb = (uint32_t)ks * 32;
            uint32_t ah[4][4], al[4][4], bh[4][2], bl[4][2];
#pragma unroll
            for (int mt = 0; mt < 4; mt++) {
                uint32_t a = stb + swz64(rowA[mt] + kb + chA);
                ldsm_x4(a, ah[mt]);
                ldsm_x4(a + 8192, al[mt]);
            }
#pragma unroll
            for (int np = 0; np < 2; np++) {
                uint32_t a = stb + 2 * 8192 + swz64(rowB[np] + kb + chB);
                uint32_t q[4];
                ldsm_x4(a, q);
                bh[2 * np][0] = q[0]; bh[2 * np][1] = q[1];
                bh[2 * np + 1][0] = q[2]; bh[2 * np + 1][1] = q[3];
                ldsm_x4(a + 8192, q);
                bl[2 * np][0] = q[0]; bl[2 * np][1] = q[1];
                bl[2 * np + 1][0] = q[2]; bl[2 * np + 1][1] = q[3];
            }
#pragma unroll
            for (int mt = 0; mt < 4; mt++)
#pragma unroll
                for (int nt = 0; nt < 4; nt++) {
                    mma16816(acc[mt][nt], ah[mt], bh[nt]);
                    mma16816(acc[mt][nt], ah[mt], bl[nt]);
                    mma16816(acc[mt][nt], al[mt], bh[nt]);
                }
        }
    }

    const int fr = lane >> 2;
    const int fc = (lane & 3) * 2;
    Chi += (size_t)z * strideC; Clo += (size_t)z * strideC;
#pragma unroll
    for (int mt = 0; mt < 4; mt++) {
#pragma unroll
        for (int nt = 0; nt < 4; nt++) {
            int col = bn + wn + nt * 8 + fc;
            float bx = bias[col], by = bias[col + 1];
#pragma unroll
            for (int half = 0; half < 2; half++) {
                int row = bm + wm + mt * 16 + fr + half * 8;
                float vx = acc[mt][nt][2 * half] + bx;
                float vy = acc[mt][nt][2 * half + 1] + by;
                if (mode) {
                    int b = row >> 11, s = row & (S_ - 1);
                    int h = col >> 6, dk = col & 63;
                    size_t o = (((size_t)b * H_ + h) * S_ + s) * DK_ + dk;
                    __nv_bfloat16 hx, hy, lx, ly;
                    split1(vx, hx, lx); split1(vy, hy, ly);
                    *(__nv_bfloat162*)&Chi[o] = __nv_bfloat162(hx, hy);
                    *(__nv_bfloat162*)&Clo[o] = __nv_bfloat162(lx, ly);
                } else {
                    *(float2*)&Cf[(size_t)row * D_ + col] = make_float2(vx, vy);
                }
            }
        }
    }
}

// ---------------------------------------------------------------------------
// Flash attention, mma.sync, causal, unscaled.
// QK^T: 3-term split. PV: 2-term (P rounded to bf16; V split hi/lo).
// K/V tiles double-buffered via cp.async (2 stages x 32KB). Q via cp.async.
// ---------------------------------------------------------------------------
#define FQH 0
#define FQL 16384
#define FKV 32768
#define FKV_STAGE 32768
#define FSM_TOTAL (32768 + 2 * FKV_STAGE)   // 98304

__global__ __launch_bounds__(256, 2) void flash_mma(
    const __nv_bfloat16* __restrict__ Qh, const __nv_bfloat16* __restrict__ Ql,
    const __nv_bfloat16* __restrict__ Kh, const __nv_bfloat16* __restrict__ Kl,
    const __nv_bfloat16* __restrict__ Vh, const __nv_bfloat16* __restrict__ Vl,
    __nv_bfloat16* __restrict__ OutH, __nv_bfloat16* __restrict__ OutL)
{
    extern __shared__ char fsm[];
    const uint32_t sb = smem_u32(fsm);
    const int tid = threadIdx.x;
    const int lane = tid & 31;
    const int w = tid >> 5;
    const int qt = gridDim.x - 1 - blockIdx.x;     // long CTAs first
    const int h = blockIdx.y, b = blockIdx.z;
    const size_t base = ((size_t)b * H_ + h) * S_ * DK_;
    const int q0 = qt * 128;
    const int nkt = 2 * qt + 2;

    const __nv_bfloat16* kvsrc[4] = { Kh + base, Kl + base, Vh + base, Vl + base };

    // ---- prologue: Q (hi/lo) + KV stage 0 via cp.async ----
#pragma unroll
    for (int i = 0; i < 4; i++) {
        int idx = i * 256 + tid;
        int row = idx >> 3, ch = idx & 7;
        uint32_t sw = swz128((uint32_t)row * 128 + ch * 16);
        cp16(sb + FQH + sw, Qh + base + (size_t)(q0 + row) * DK_ + ch * 8);
        cp16(sb + FQL + sw, Ql + base + (size_t)(q0 + row) * DK_ + ch * 8);
    }
    {
        const uint32_t s0 = sb + FKV;
#pragma unroll
        for (int t = 0; t < 4; t++)
#pragma unroll
            for (int half = 0; half < 2; half++) {
                int ci = half * 256 + tid;
                int row = ci >> 3, ch = ci & 7;
                cp16(s0 + t * 8192 + swz128((uint32_t)row * 128 + ch * 16),
                     kvsrc[t] + (size_t)row * DK_ + ch * 8);
            }
    }
    CP_COMMIT();

    float o[8][4];
#pragma unroll
    for (int nt = 0; nt < 8; nt++)
#pragma unroll
        for (int r = 0; r < 4; r++) o[nt][r] = 0.f;
    float m0 = -INFINITY, m1 = -INFINITY, l0 = 0.f, l1 = 0.f;

    const int g = lane >> 3, r8 = lane & 7;
    const uint32_t qrow = (uint32_t)(w * 16 + (g & 1) * 8 + r8) * 128 + (uint32_t)(g >> 1) * 16;
    const uint32_t krow = (uint32_t)((g >> 1) * 8 + r8) * 128 + (uint32_t)(g & 1) * 16;
    const uint32_t vrow = (uint32_t)((lane & 7) + ((lane >> 3) & 1) * 8) * 128
                        + (uint32_t)(lane >> 4) * 16;
    const int wq = q0 + w * 16;

    for (int kt = 0; kt < nkt; kt++) {
        const uint32_t stg = sb + FKV + (uint32_t)(kt & 1) * FKV_STAGE;
        CP_WAIT0();
        __syncthreads();

        // prefetch next KV tile into other stage (overlaps compute below)
        if (kt + 1 < nkt) {
            const int nk0 = (kt + 1) * 64;
            const uint32_t ns = sb + FKV + (uint32_t)((kt + 1) & 1) * FKV_STAGE;
#pragma unroll
            for (int t = 0; t < 4; t++)
#pragma unroll
                for (int half = 0; half < 2; half++) {
                    int ci = half * 256 + tid;
                    int row = ci >> 3, ch = ci & 7;
                    cp16(ns + t * 8192 + swz128((uint32_t)row * 128 + ch * 16),
                         kvsrc[t] + (size_t)(nk0 + row) * DK_ + ch * 8);
                }
            CP_COMMIT();
        }

        // ---- S = Q K^T (3-term split) ----
        float s[8][4];
#pragma unroll
        for (int nt = 0; nt < 8; nt++)
#pragma unroll
            for (int r = 0; r < 4; r++) s[nt][r] = 0.f;

#pragma unroll
        for (int ks = 0; ks < 4; ks++) {
            uint32_t qh_f[4], ql_f[4];
            uint32_t qa = sb + FQH + swz128(qrow + ks * 32);
            ldsm_x4(qa, qh_f);
            ldsm_x4(qa + (FQL - FQH), ql_f);
#pragma unroll
            for (int np = 0; np < 4; np++) {
                uint32_t ka = stg + swz128(krow + (uint32_t)np * 16 * 128 + ks * 32);
                uint32_t rh[4], rl[4];
                ldsm_x4(ka, rh);
                ldsm_x4(ka + 8192, rl);
                uint32_t bh0[2] = { rh[0], rh[1] }, bh1[2] = { rh[2], rh[3] };
                uint32_t bl0[2] = { rl[0], rl[1] }, bl1[2] = { rl[2], rl[3] };
                mma16816(s[2 * np],     qh_f, bh0);
                mma16816(s[2 * np],     qh_f, bl0);
                mma16816(s[2 * np],     ql_f, bh0);
                mma16816(s[2 * np + 1], qh_f, bh1);
                mma16816(s[2 * np + 1], qh_f, bl1);
                mma16816(s[2 * np + 1], ql_f, bh1);
            }
        }

        const int k0 = kt * 64;
        if (k0 + 63 > wq) {
            int r0g = wq + (lane >> 2), r1g = r0g + 8;
            int cb = k0 + 2 * (lane & 3);
#pragma unroll
            for (int nt = 0; nt < 8; nt++) {
                int key = cb + nt * 8;
                if (key     > r0g) s[nt][0] = -1e9f;
                if (key + 1 > r0g) s[nt][1] = -1e9f;
                if (key     > r1g) s[nt][2] = -1e9f;
                if (key + 1 > r1g) s[nt][3] = -1e9f;
            }
        }

        // ---- online softmax ----
        float rm0 = -INFINITY, rm1 = -INFINITY;
#pragma unroll
        for (int nt = 0; nt < 8; nt++) {
            rm0 = fmaxf(rm0, fmaxf(s[nt][0], s[nt][1]));
            rm1 = fmaxf(rm1, fmaxf(s[nt][2], s[nt][3]));
        }
        rm0 = fmaxf(rm0, __shfl_xor_sync(0xffffffffu, rm0, 1));
        rm0 = fmaxf(rm0, __shfl_xor_sync(0xffffffffu, rm0, 2));
        rm1 = fmaxf(rm1, __shfl_xor_sync(0xffffffffu, rm1, 1));
        rm1 = fmaxf(rm1, __shfl_xor_sync(0xffffffffu, rm1, 2));
        float mn0 = fmaxf(m0, rm0), mn1 = fmaxf(m1, rm1);
        float sc0 = __expf(m0 - mn0), sc1 = __expf(m1 - mn1);
        float rs0 = 0.f, rs1 = 0.f;
#pragma unroll
        for (int nt = 0; nt < 8; nt++) {
            s[nt][0] = __expf(s[nt][0] - mn0);
            s[nt][1] = __expf(s[nt][1] - mn0);
            s[nt][2] = __expf(s[nt][2] - mn1);
            s[nt][3] = __expf(s[nt][3] - mn1);
            rs0 += s[nt][0] + s[nt][1];
            rs1 += s[nt][2] + s[nt][3];
        }
        rs0 += __shfl_xor_sync(0xffffffffu, rs0, 1);
        rs0 += __shfl_xor_sync(0xffffffffu, rs0, 2);
        rs1 += __shfl_xor_sync(0xffffffffu, rs1, 1);
        rs1 += __shfl_xor_sync(0xffffffffu, rs1, 2);
        l0 = l0 * sc0 + rs0; m0 = mn0;
        l1 = l1 * sc1 + rs1; m1 = mn1;
#pragma unroll
        for (int nt = 0; nt < 8; nt++) {
            o[nt][0] *= sc0; o[nt][1] *= sc0;
            o[nt][2] *= sc1; o[nt][3] *= sc1;
        }

        // ---- O += P V  (P rounded bf16; V = Vh + Vl) ----
#pragma unroll
        for (int ks = 0; ks < 4; ks++) {
            uint32_t aph[4];
#pragma unroll
            for (int half = 0; half < 2; half++) {
                int st = 2 * ks + half;
                __nv_bfloat162 p01 = __floats2bfloat162_rn(s[st][0], s[st][1]);
                __nv_bfloat162 p23 = __floats2bfloat162_rn(s[st][2], s[st][3]);
                aph[2 * half]     = *(uint32_t*)&p01;
                aph[2 * half + 1] = *(uint32_t*)&p23;
            }
#pragma unroll
            for (int vb = 0; vb < 4; vb++) {
                uint32_t va = stg + 2 * 8192 + swz128(vrow + (uint32_t)ks * 16 * 128 + vb * 32);
                uint32_t rh[4], rl[4];
                ldsm_x4_t(va, rh);
                ldsm_x4_t(va + 8192, rl);
                uint32_t bh0[2] = { rh[0], rh[1] }, bh1[2] = { rh[2], rh[3] };
                uint32_t bl0[2] = { rl[0], rl[1] }, bl1[2] = { rl[2], rl[3] };
                mma16816(o[2 * vb],     aph, bh0);
                mma16816(o[2 * vb],     aph, bl0);
                mma16816(o[2 * vb + 1], aph, bh1);
                mma16816(o[2 * vb + 1], aph, bl1);
            }
        }
    }

    float inv0 = 1.f / l0, inv1 = 1.f / l1;
    int row0 = b * S_ + q0 + w * 16 + (lane >> 2);
    int row1 = row0 + 8;
    int colb = h * 64 + 2 * (lane & 3);
#pragma unroll
    for (int nt = 0; nt < 8; nt++) {
        int col = colb + nt * 8;
        float v0 = o[nt][0] * inv0, v1 = o[nt][1] * inv0;
        float v2 = o[nt][2] * inv1, v3 = o[nt][3] * inv1;
        __nv_bfloat16 hx, hy, lx, ly;
        split1(v0, hx, lx); split1(v1, hy, ly);
        *(__nv_bfloat162*)&OutH[(size_t)row0 * D_ + col] = __nv_bfloat162(hx, hy);
        *(__nv_bfloat162*)&OutL[(size_t)row0 * D_ + col] = __nv_bfloat162(lx, ly);
        split1(v2, hx, lx); split1(v3, hy, ly);
        *(__nv_bfloat162*)&OutH[(size_t)row1 * D_ + col] = __nv_bfloat162(hx, hy);
        *(__nv_bfloat162*)&OutL[(size_t)row1 * D_ + col] = __nv_bfloat162(lx, ly);
    }
}

// ---------------------------------------------------------------------------
extern "C" void kernel_launch(void* const* d_in, const int* in_sizes, int n_in,
                              void* d_out, int out_size)
{
    const float* Q  = (const float*)d_in[0];
    const float* K  = (const float*)d_in[1];
    const float* V  = (const float*)d_in[2];
    // d_in[3] = Mask (guaranteed tril -> hardcoded causal)
    const float* Wq = (const float*)d_in[4];
    const float* bq = (const float*)d_in[5];
    const float* Wk = (const float*)d_in[6];
    const float* bk = (const float*)d_in[7];
    const float* Wv = (const float*)d_in[8];
    const float* bv = (const float*)d_in[9];
    const float* Wo = (const float*)d_in[10];
    const float* bo = (const float*)d_in[11];
    float* out = (float*)d_out;

    __nv_bfloat16 *ah, *al, *wh, *wl, *qkvh, *qkvl;
    cudaGetSymbolAddress((void**)&ah, g_ah);
    cudaGetSymbolAddress((void**)&al, g_al);
    cudaGetSymbolAddress((void**)&wh, g_wh);
    cudaGetSymbolAddress((void**)&wl, g_wl);
    cudaGetSymbolAddress((void**)&qkvh, g_qkvh);
    cudaGetSymbolAddress((void**)&qkvl, g_qkvl);

    static bool attr_done = false;
    if (!attr_done) {
        cudaFuncSetAttribute(mma_gemm, cudaFuncAttributeMaxDynamicSharedMemorySize, GSM_TOTAL);
        cudaFuncSetAttribute(flash_mma, cudaFuncAttributeMaxDynamicSharedMemorySize, FSM_TOTAL);
        attr_done = true;
    }

    In4 ws = { Wq, Wk, Wv, Wo };
    split_w<<<dim3(NW_ / 1024, 4), 256>>>(ws, wh, wl);
    In3 xs = { Q, K, V };
    split_qkv<<<dim3(NA_ / 1024, 3), 256>>>(xs, ah, al);

    Bias3 bqkv = { bq, bk, bv };
    mma_gemm<<<dim3(D_ / 128, M_ / 128, 3), 256, GSM_TOTAL>>>(
        ah, al, NA_, wh, wl, NW_, bqkv, qkvh, qkvl, BHS_, nullptr, 1);

    flash_mma<<<dim3(S_ / 128, H_, B_), 256, FSM_TOTAL>>>(
        qkvh, qkvl, qkvh + BHS_, qkvl + BHS_, qkvh + 2 * BHS_, qkvl + 2 * BHS_, ah, al);

    Bias3 bout = { bo, bo, bo };
    mma_gemm<<<dim3(D_ / 128, M_ / 128, 1), 256, GSM_TOTAL>>>(
        ah, al, 0, wh + 3 * (size_t)NW_, wl + 3 * (size_t)NW_, 0, bout,
        nullptr, nullptr, 0, out, 0);
}

// round 7
// speedup vs baseline: 3.8419x; 1.0093x over previous
#include <cuda_runtime.h>
#include <cuda_bf16.h>
#include <math.h>
#include <stdint.h>

#define B_  2
#define S_  2048
#define D_  1024
#define H_  16
#define DK_ 64
#define M_  (B_ * S_)                 // 4096
#define NA_ (M_ * D_)                 // 4194304
#define NW_ (D_ * D_)                 // 1048576
#define BHS_ (B_ * H_ * S_ * DK_)     // 4194304

// ---------------------------------------------------------------------------
// Scratch (allocation-free rule: __device__ globals)
// ---------------------------------------------------------------------------
__device__ __nv_bfloat16 g_ah[3 * NA_];
__device__ __nv_bfloat16 g_al[3 * NA_];
__device__ __nv_bfloat16 g_wh[4 * NW_];
__device__ __nv_bfloat16 g_wl[4 * NW_];
__device__ __nv_bfloat16 g_qkvh[3 * BHS_];
__device__ __nv_bfloat16 g_qkvl[3 * BHS_];

struct Bias3 { const float* b0; const float* b1; const float* b2; };
struct In3   { const float* x0; const float* x1; const float* x2; };
struct In4   { const float* x0; const float* x1; const float* x2; const float* x3; };

// ---------------------------------------------------------------------------
// helpers
// ---------------------------------------------------------------------------
__device__ __forceinline__ uint32_t smem_u32(const void* p) {
    uint32_t a;
    asm("{ .reg .u64 t; cvta.to.shared.u64 t, %1; cvt.u32.u64 %0, t; }"
        : "=r"(a) : "l"(p));
    return a;
}
__device__ __forceinline__ void ldsm_x4(uint32_t addr, uint32_t* r) {
    asm volatile("ldmatrix.sync.aligned.m8n8.x4.shared.b16 {%0,%1,%2,%3}, [%4];"
        : "=r"(r[0]), "=r"(r[1]), "=r"(r[2]), "=r"(r[3]) : "r"(addr));
}
__device__ __forceinline__ void ldsm_x4_t(uint32_t addr, uint32_t* r) {
    asm volatile("ldmatrix.sync.aligned.m8n8.x4.trans.shared.b16 {%0,%1,%2,%3}, [%4];"
        : "=r"(r[0]), "=r"(r[1]), "=r"(r[2]), "=r"(r[3]) : "r"(addr));
}
__device__ __forceinline__ void mma16816(float* d, const uint32_t* a, const uint32_t* b) {
    asm volatile("mma.sync.aligned.m16n8k16.row.col.f32.bf16.bf16.f32 "
        "{%0,%1,%2,%3}, {%4,%5,%6,%7}, {%8,%9}, {%0,%1,%2,%3};"
        : "+f"(d[0]), "+f"(d[1]), "+f"(d[2]), "+f"(d[3])
        : "r"(a[0]), "r"(a[1]), "r"(a[2]), "r"(a[3]), "r"(b[0]), "r"(b[1]));
}
__device__ __forceinline__ void cp16(uint32_t d, const void* g) {
    asm volatile("cp.async.cg.shared.global [%0], [%1], 16;" :: "r"(d), "l"(g));
}
#define CP_COMMIT() asm volatile("cp.async.commit_group;")
#define CP_WAIT0()  asm volatile("cp.async.wait_group 0;")

__device__ __forceinline__ uint32_t swz64(uint32_t b)  { return b ^ ((b >> 3) & 0x30); }
__device__ __forceinline__ uint32_t swz128(uint32_t b) { return b ^ ((b >> 3) & 0x70); }
__device__ __forceinline__ void split1(float v, __nv_bfloat16& h, __nv_bfloat16& l) {
    h = __float2bfloat16(v);
    l = __float2bfloat16(v - __bfloat162float(h));
}

// ---------------------------------------------------------------------------
// fused splits
// ---------------------------------------------------------------------------
__global__ __launch_bounds__(256) void split_qkv(In3 in, __nv_bfloat16* __restrict__ hi,
                                                 __nv_bfloat16* __restrict__ lo)
{
    int z = blockIdx.y;
    const float* x = (z == 0) ? in.x0 : (z == 1) ? in.x1 : in.x2;
    size_t off = (size_t)z * NA_;
    int i = (blockIdx.x * 256 + threadIdx.x) * 4;
    float4 v = *(const float4*)(x + i);
    __nv_bfloat16 h0, h1, h2, h3, l0, l1, l2, l3;
    split1(v.x, h0, l0); split1(v.y, h1, l1);
    split1(v.z, h2, l2); split1(v.w, h3, l3);
    __nv_bfloat162* hp = (__nv_bfloat162*)(hi + off + i);
    __nv_bfloat162* lp = (__nv_bfloat162*)(lo + off + i);
    hp[0] = __nv_bfloat162(h0, h1); hp[1] = __nv_bfloat162(h2, h3);
    lp[0] = __nv_bfloat162(l0, l1); lp[1] = __nv_bfloat162(l2, l3);
}

__global__ __launch_bounds__(256) void split_w(In4 in, __nv_bfloat16* __restrict__ hi,
                                               __nv_bfloat16* __restrict__ lo)
{
    int z = blockIdx.y;
    const float* x = (z == 0) ? in.x0 : (z == 1) ? in.x1 : (z == 2) ? in.x2 : in.x3;
    size_t off = (size_t)z * NW_;
    int i = (blockIdx.x * 256 + threadIdx.x) * 4;
    float4 v = *(const float4*)(x + i);
    __nv_bfloat16 h0, h1, h2, h3, l0, l1, l2, l3;
    split1(v.x, h0, l0); split1(v.y, h1, l1);
    split1(v.z, h2, l2); split1(v.w, h3, l3);
    __nv_bfloat162* hp = (__nv_bfloat162*)(hi + off + i);
    __nv_bfloat162* lp = (__nv_bfloat162*)(lo + off + i);
    hp[0] = __nv_bfloat162(h0, h1); hp[1] = __nv_bfloat162(h2, h3);
    lp[0] = __nv_bfloat162(l0, l1); lp[1] = __nv_bfloat162(l2, l3);
}

// ---------------------------------------------------------------------------
// Tensor-core GEMM (split bf16, cp.async 2-stage, batched over z) — as R6
// ---------------------------------------------------------------------------
#define GSM_STAGE 32768
#define GSM_TOTAL 65536

__global__ __launch_bounds__(256) void mma_gemm(
    const __nv_bfloat16* __restrict__ Ah, const __nv_bfloat16* __restrict__ Al,
    size_t strideA,
    const __nv_bfloat16* __restrict__ Wh, const __nv_bfloat16* __restrict__ Wl,
    size_t strideW, Bias3 bs,
    __nv_bfloat16* __restrict__ Chi, __nv_bfloat16* __restrict__ Clo, size_t strideC,
    float* __restrict__ Cf, int mode)
{
    extern __shared__ char sm[];
    const uint32_t sb = smem_u32(sm);
    const int tid = threadIdx.x;
    const int lane = tid & 31;
    const int wid = tid >> 5;
    const int z = blockIdx.z;
    const int bm = blockIdx.y * 128;
    const int bn = blockIdx.x * 128;
    const int wm = (wid & 1) * 64;
    const int wn = (wid >> 1) * 32;

    const float* bias = (z == 0) ? bs.b0 : (z == 1) ? bs.b1 : bs.b2;
    Ah += (size_t)z * strideA; Al += (size_t)z * strideA;
    Wh += (size_t)z * strideW; Wl += (size_t)z * strideW;

    float acc[4][4][4];
#pragma unroll
    for (int mt = 0; mt < 4; mt++)
#pragma unroll
        for (int nt = 0; nt < 4; nt++)
#pragma unroll
            for (int r = 0; r < 4; r++) acc[mt][nt][r] = 0.f;

    const int g = lane >> 3, r8 = lane & 7;
    uint32_t rowA[4], rowB[2];
#pragma unroll
    for (int mt = 0; mt < 4; mt++)
        rowA[mt] = (uint32_t)(wm + mt * 16 + (g & 1) * 8 + r8) * 64;
#pragma unroll
    for (int np = 0; np < 2; np++)
        rowB[np] = (uint32_t)(wn + np * 16 + (g >> 1) * 8 + r8) * 64;
    const uint32_t chA = (uint32_t)(g >> 1) * 16;
    const uint32_t chB = (uint32_t)(g & 1) * 16;

    const int gl_row0 = tid >> 2, gl_c0 = tid & 3;
    const int gl_row1 = (tid + 256) >> 2, gl_c1 = tid & 3;
    const uint32_t st0 = swz64((uint32_t)gl_row0 * 64 + gl_c0 * 16);
    const uint32_t st1 = swz64((uint32_t)gl_row1 * 64 + gl_c1 * 16);

    const __nv_bfloat16* srcs[4] = { Ah, Al, Wh, Wl };
    const int rbase[4] = { bm, bm, bn, bn };

#pragma unroll
    for (int t = 0; t < 4; t++) {
        const __nv_bfloat16* s = srcs[t];
        cp16(sb + t * 8192 + st0, s + (size_t)(rbase[t] + gl_row0) * D_ + gl_c0 * 8);
        cp16(sb + t * 8192 + st1, s + (size_t)(rbase[t] + gl_row1) * D_ + gl_c1 * 8);
    }
    CP_COMMIT();

    for (int kt = 0; kt < 32; kt++) {
        const uint32_t stb = sb + (uint32_t)(kt & 1) * GSM_STAGE;
        CP_WAIT0();
        __syncthreads();

        if (kt + 1 < 32) {
            const int k0 = (kt + 1) * 32;
            const uint32_t nstb = sb + (uint32_t)((kt + 1) & 1) * GSM_STAGE;
#pragma unroll
            for (int t = 0; t < 4; t++) {
                const __nv_bfloat16* s = srcs[t];
                cp16(nstb + t * 8192 + st0, s + (size_t)(rbase[t] + gl_row0) * D_ + k0 + gl_c0 * 8);
                cp16(nstb + t * 8192 + st1, s + (size_t)(rbase[t] + gl_row1) * D_ + k0 + gl_c1 * 8);
            }
            CP_COMMIT();
        }

#pragma unroll
        for (int ks = 0; ks < 2; ks++) {
            const uint32_t kb = (uint32_t)ks * 32;
            uint32_t ah[4][4], al[4][4], bh[4][2], bl[4][2];
#pragma unroll
            for (int mt = 0; mt < 4; mt++) {
                uint32_t a = stb + swz64(rowA[mt] + kb + chA);
                ldsm_x4(a, ah[mt]);
                ldsm_x4(a + 8192, al[mt]);
            }
#pragma unroll
            for (int np = 0; np < 2; np++) {
                uint32_t a = stb + 2 * 8192 + swz64(rowB[np] + kb + chB);
                uint32_t q[4];
                ldsm_x4(a, q);
                bh[2 * np][0] = q[0]; bh[2 * np][1] = q[1];
                bh[2 * np + 1][0] = q[2]; bh[2 * np + 1][1] = q[3];
                ldsm_x4(a + 8192, q);
                bl[2 * np][0] = q[0]; bl[2 * np][1] = q[1];
                bl[2 * np + 1][0] = q[2]; bl[2 * np + 1][1] = q[3];
            }
#pragma unroll
            for (int mt = 0; mt < 4; mt++)
#pragma unroll
                for (int nt = 0; nt < 4; nt++) {
                    mma16816(acc[mt][nt], ah[mt], bh[nt]);
                    mma16816(acc[mt][nt], ah[mt], bl[nt]);
                    mma16816(acc[mt][nt], al[mt], bh[nt]);
                }
        }
    }

    const int fr = lane >> 2;
    const int fc = (lane & 3) * 2;
    Chi += (size_t)z * strideC; Clo += (size_t)z * strideC;
#pragma unroll
    for (int mt = 0; mt < 4; mt++) {
#pragma unroll
        for (int nt = 0; nt < 4; nt++) {
            int col = bn + wn + nt * 8 + fc;
            float bx = bias[col], by = bias[col + 1];
#pragma unroll
            for (int half = 0; half < 2; half++) {
                int row = bm + wm + mt * 16 + fr + half * 8;
                float vx = acc[mt][nt][2 * half] + bx;
                float vy = acc[mt][nt][2 * half + 1] + by;
                if (mode) {
                    int b = row >> 11, s = row & (S_ - 1);
                    int h = col >> 6, dk = col & 63;
                    size_t o = (((size_t)b * H_ + h) * S_ + s) * DK_ + dk;
                    __nv_bfloat16 hx, hy, lx, ly;
                    split1(vx, hx, lx); split1(vy, hy, ly);
                    *(__nv_bfloat162*)&Chi[o] = __nv_bfloat162(hx, hy);
                    *(__nv_bfloat162*)&Clo[o] = __nv_bfloat162(lx, ly);
                } else {
                    *(float2*)&Cf[(size_t)row * D_ + col] = make_float2(vx, vy);
                }
            }
        }
    }
}

// ---------------------------------------------------------------------------
// Flash attention, mma.sync, causal, unscaled — tile-level software pipeline:
//   per iter kt: softmax(S(kt)) -> [QK(kt+1) interleaved with PV(kt)]
// K and V in separate double-buffered rings (K prefetch 1 tile ahead of V).
// QK^T: 3-term split; PV: 2-term (P bf16, V hi+lo).
// ---------------------------------------------------------------------------
#define FQH 0
#define FQL 16384
#define FKS 32768            // K ring: 2 stages x 16384 (Kh 8K + Kl 8K)
#define FVS 65536            // V ring: 2 stages x 16384
#define FSTG 16384
#define FSM_TOTAL 98304

__global__ __launch_bounds__(256) void flash_mma(
    const __nv_bfloat16* __restrict__ Qh, const __nv_bfloat16* __restrict__ Ql,
    const __nv_bfloat16* __restrict__ Kh, const __nv_bfloat16* __restrict__ Kl,
    const __nv_bfloat16* __restrict__ Vh, const __nv_bfloat16* __restrict__ Vl,
    __nv_bfloat16* __restrict__ OutH, __nv_bfloat16* __restrict__ OutL)
{
    extern __shared__ char fsm[];
    const uint32_t sb = smem_u32(fsm);
    const int tid = threadIdx.x;
    const int lane = tid & 31;
    const int w = tid >> 5;
    const int qt = gridDim.x - 1 - blockIdx.x;     // long CTAs first
    const int h = blockIdx.y, b = blockIdx.z;
    const size_t base = ((size_t)b * H_ + h) * S_ * DK_;
    const int q0 = qt * 128;
    const int nkt = 2 * qt + 2;

    const __nv_bfloat16* ksrc[2] = { Kh + base, Kl + base };
    const __nv_bfloat16* vsrc[2] = { Vh + base, Vl + base };

    // cp.async a 64-row hi/lo tile pair (16KB) into dst
    auto ldkv = [&](const __nv_bfloat16* const* src, uint32_t dst, int k0) {
#pragma unroll
        for (int t = 0; t < 2; t++)
#pragma unroll
            for (int half = 0; half < 2; half++) {
                int ci = half * 256 + tid;
                int row = ci >> 3, ch = ci & 7;
                cp16(dst + t * 8192 + swz128((uint32_t)row * 128 + ch * 16),
                     src[t] + (size_t)(k0 + row) * DK_ + ch * 8);
            }
    };

    // ---- prologue: Q hi/lo, K(0), V(0), K(1) ----
#pragma unroll
    for (int i = 0; i < 4; i++) {
        int idx = i * 256 + tid;
        int row = idx >> 3, ch = idx & 7;
        uint32_t sw = swz128((uint32_t)row * 128 + ch * 16);
        cp16(sb + FQH + sw, Qh + base + (size_t)(q0 + row) * DK_ + ch * 8);
        cp16(sb + FQL + sw, Ql + base + (size_t)(q0 + row) * DK_ + ch * 8);
    }
    ldkv(ksrc, sb + FKS, 0);
    ldkv(vsrc, sb + FVS, 0);
    if (nkt > 1) ldkv(ksrc, sb + FKS + FSTG, 64);
    CP_COMMIT(); CP_WAIT0(); __syncthreads();

    float o[8][4], s[8][4];
#pragma unroll
    for (int nt = 0; nt < 8; nt++)
#pragma unroll
        for (int r = 0; r < 4; r++) { o[nt][r] = 0.f; s[nt][r] = 0.f; }
    float m0 = -INFINITY, m1 = -INFINITY, l0 = 0.f, l1 = 0.f;

    const int g = lane >> 3, r8 = lane & 7;
    const uint32_t qrow = (uint32_t)(w * 16 + (g & 1) * 8 + r8) * 128 + (uint32_t)(g >> 1) * 16;
    const uint32_t krow = (uint32_t)((g >> 1) * 8 + r8) * 128 + (uint32_t)(g & 1) * 16;
    const uint32_t vrow = (uint32_t)((lane & 7) + ((lane >> 3) & 1) * 8) * 128
                        + (uint32_t)(lane >> 4) * 16;
    const int wq = q0 + w * 16;

    // one k16-chunk of QK (3-term) into acc
    auto qk_chunk = [&](float (*acc)[4], int ks, uint32_t kstg) {
        uint32_t qh_f[4], ql_f[4];
        uint32_t qa = sb + FQH + swz128(qrow + (uint32_t)ks * 32);
        ldsm_x4(qa, qh_f);
        ldsm_x4(qa + (FQL - FQH), ql_f);
#pragma unroll
        for (int np = 0; np < 4; np++) {
            uint32_t ka = kstg + swz128(krow + (uint32_t)np * 2048 + (uint32_t)ks * 32);
            uint32_t rh[4], rl[4];
            ldsm_x4(ka, rh);
            ldsm_x4(ka + 8192, rl);
            uint32_t bh0[2] = { rh[0], rh[1] }, bh1[2] = { rh[2], rh[3] };
            uint32_t bl0[2] = { rl[0], rl[1] }, bl1[2] = { rl[2], rl[3] };
            mma16816(acc[2 * np],     qh_f, bh0);
            mma16816(acc[2 * np],     qh_f, bl0);
            mma16816(acc[2 * np],     ql_f, bh0);
            mma16816(acc[2 * np + 1], qh_f, bh1);
            mma16816(acc[2 * np + 1], qh_f, bl1);
            mma16816(acc[2 * np + 1], ql_f, bh1);
        }
    };
    // one k16-chunk of PV (2-term) into o
    auto pv_chunk = [&](const uint32_t* pks, int ks, uint32_t vstg) {
#pragma unroll
        for (int vb = 0; vb < 4; vb++) {
            uint32_t va = vstg + swz128(vrow + (uint32_t)ks * 2048 + (uint32_t)vb * 32);
            uint32_t rh[4], rl[4];
            ldsm_x4_t(va, rh);
            ldsm_x4_t(va + 8192, rl);
            uint32_t bh0[2] = { rh[0], rh[1] }, bh1[2] = { rh[2], rh[3] };
            uint32_t bl0[2] = { rl[0], rl[1] }, bl1[2] = { rl[2], rl[3] };
            mma16816(o[2 * vb],     pks, bh0);
            mma16816(o[2 * vb],     pks, bl0);
            mma16816(o[2 * vb + 1], pks, bh1);
            mma16816(o[2 * vb + 1], pks, bl1);
        }
    };

    // ---- S = QK(0) ----
#pragma unroll
    for (int ks = 0; ks < 4; ks++) qk_chunk(s, ks, sb + FKS);

    for (int kt = 0; kt < nkt; kt++) {
        const int k0 = kt * 64;

        // ---- mask (diagonal tiles only) ----
        if (k0 + 63 > wq) {
            int r0g = wq + (lane >> 2), r1g = r0g + 8;
            int cb = k0 + 2 * (lane & 3);
#pragma unroll
            for (int nt = 0; nt < 8; nt++) {
                int key = cb + nt * 8;
                if (key     > r0g) s[nt][0] = -1e9f;
                if (key + 1 > r0g) s[nt][1] = -1e9f;
                if (key     > r1g) s[nt][2] = -1e9f;
                if (key + 1 > r1g) s[nt][3] = -1e9f;
            }
        }

        // ---- online softmax; build packed P; free s for reuse ----
        float rm0 = -INFINITY, rm1 = -INFINITY;
#pragma unroll
        for (int nt = 0; nt < 8; nt++) {
            rm0 = fmaxf(rm0, fmaxf(s[nt][0], s[nt][1]));
            rm1 = fmaxf(rm1, fmaxf(s[nt][2], s[nt][3]));
        }
        rm0 = fmaxf(rm0, __shfl_xor_sync(0xffffffffu, rm0, 1));
        rm0 = fmaxf(rm0, __shfl_xor_sync(0xffffffffu, rm0, 2));
        rm1 = fmaxf(rm1, __shfl_xor_sync(0xffffffffu, rm1, 1));
        rm1 = fmaxf(rm1, __shfl_xor_sync(0xffffffffu, rm1, 2));
        float mn0 = fmaxf(m0, rm0), mn1 = fmaxf(m1, rm1);
        float sc0 = __expf(m0 - mn0), sc1 = __expf(m1 - mn1);
        float rs0 = 0.f, rs1 = 0.f;
        uint32_t p[4][4];
#pragma unroll
        for (int nt = 0; nt < 8; nt++) {
            float e0 = __expf(s[nt][0] - mn0);
            float e1 = __expf(s[nt][1] - mn0);
            float e2 = __expf(s[nt][2] - mn1);
            float e3 = __expf(s[nt][3] - mn1);
            rs0 += e0 + e1; rs1 += e2 + e3;
            __nv_bfloat162 p01 = __floats2bfloat162_rn(e0, e1);
            __nv_bfloat162 p23 = __floats2bfloat162_rn(e2, e3);
            int ks = nt >> 1, half = nt & 1;
            p[ks][2 * half]     = *(uint32_t*)&p01;
            p[ks][2 * half + 1] = *(uint32_t*)&p23;
        }
        rs0 += __shfl_xor_sync(0xffffffffu, rs0, 1);
        rs0 += __shfl_xor_sync(0xffffffffu, rs0, 2);
        rs1 += __shfl_xor_sync(0xffffffffu, rs1, 1);
        rs1 += __shfl_xor_sync(0xffffffffu, rs1, 2);
        l0 = l0 * sc0 + rs0; m0 = mn0;
        l1 = l1 * sc1 + rs1; m1 = mn1;
#pragma unroll
        for (int nt = 0; nt < 8; nt++) {
            o[nt][0] *= sc0; o[nt][1] *= sc0;
            o[nt][2] *= sc1; o[nt][3] *= sc1;
        }

        // ---- prefetch K(kt+2), V(kt+1) ----
        if (kt + 2 < nkt) ldkv(ksrc, sb + FKS + (uint32_t)(kt & 1) * FSTG, (kt + 2) * 64);
        if (kt + 1 < nkt) ldkv(vsrc, sb + FVS + (uint32_t)((kt + 1) & 1) * FSTG, (kt + 1) * 64);
        CP_COMMIT();

        // ---- interleaved: S(kt+1) = QK(kt+1)  ||  O += P(kt) V(kt) ----
#pragma unroll
        for (int nt = 0; nt < 8; nt++)
#pragma unroll
            for (int r = 0; r < 4; r++) s[nt][r] = 0.f;
        const bool doqk = (kt + 1 < nkt);
        const uint32_t kstg = sb + FKS + (uint32_t)((kt + 1) & 1) * FSTG;
        const uint32_t vstg = sb + FVS + (uint32_t)(kt & 1) * FSTG;
#pragma unroll
        for (int ks = 0; ks < 4; ks++) {
            if (doqk) qk_chunk(s, ks, kstg);
            pv_chunk(p[ks], ks, vstg);
        }

        CP_WAIT0(); __syncthreads();
    }

    // ---- epilogue ----
    float inv0 = 1.f / l0, inv1 = 1.f / l1;
    int row0 = b * S_ + q0 + w * 16 + (lane >> 2);
    int row1 = row0 + 8;
    int colb = h * 64 + 2 * (lane & 3);
#pragma unroll
    for (int nt = 0; nt < 8; nt++) {
        int col = colb + nt * 8;
        float v0 = o[nt][0] * inv0, v1 = o[nt][1] * inv0;
        float v2 = o[nt][2] * inv1, v3 = o[nt][3] * inv1;
        __nv_bfloat16 hx, hy, lx, ly;
        split1(v0, hx, lx); split1(v1, hy, ly);
        *(__nv_bfloat162*)&OutH[(size_t)row0 * D_ + col] = __nv_bfloat162(hx, hy);
        *(__nv_bfloat162*)&OutL[(size_t)row0 * D_ + col] = __nv_bfloat162(lx, ly);
        split1(v2, hx, lx); split1(v3, hy, ly);
        *(__nv_bfloat162*)&OutH[(size_t)row1 * D_ + col] = __nv_bfloat162(hx, hy);
        *(__nv_bfloat162*)&OutL[(size_t)row1 * D_ + col] = __nv_bfloat162(lx, ly);
    }
}

// ---------------------------------------------------------------------------
extern "C" void kernel_launch(void* const* d_in, const int* in_sizes, int n_in,
                              void* d_out, int out_size)
{
    const float* Q  = (const float*)d_in[0];
    const float* K  = (const float*)d_in[1];
    const float* V  = (const float*)d_in[2];
    // d_in[3] = Mask (guaranteed tril -> hardcoded causal)
    const float* Wq = (const float*)d_in[4];
    const float* bq = (const float*)d_in[5];
    const float* Wk = (const float*)d_in[6];
    const float* bk = (const float*)d_in[7];
    const float* Wv = (const float*)d_in[8];
    const float* bv = (const float*)d_in[9];
    const float* Wo = (const float*)d_in[10];
    const float* bo = (const float*)d_in[11];
    float* out = (float*)d_out;

    __nv_bfloat16 *ah, *al, *wh, *wl, *qkvh, *qkvl;
    cudaGetSymbolAddress((void**)&ah, g_ah);
    cudaGetSymbolAddress((void**)&al, g_al);
    cudaGetSymbolAddress((void**)&wh, g_wh);
    cudaGetSymbolAddress((void**)&wl, g_wl);
    cudaGetSymbolAddress((void**)&qkvh, g_qkvh);
    cudaGetSymbolAddress((void**)&qkvl, g_qkvl);

    static bool attr_done = false;
    if (!attr_done) {
        cudaFuncSetAttribute(mma_gemm, cudaFuncAttributeMaxDynamicSharedMemorySize, GSM_TOTAL);
        cudaFuncSetAttribute(flash_mma, cudaFuncAttributeMaxDynamicSharedMemorySize, FSM_TOTAL);
        attr_done = true;
    }

    In4 ws = { Wq, Wk, Wv, Wo };
    split_w<<<dim3(NW_ / 1024, 4), 256>>>(ws, wh, wl);
    In3 xs = { Q, K, V };
    split_qkv<<<dim3(NA_ / 1024, 3), 256>>>(xs, ah, al);

    Bias3 bqkv = { bq, bk, bv };
    mma_gemm<<<dim3(D_ / 128, M_ / 128, 3), 256, GSM_TOTAL>>>(
        ah, al, NA_, wh, wl, NW_, bqkv, qkvh, qkvl, BHS_, nullptr, 1);

    flash_mma<<<dim3(S_ / 128, H_, B_), 256, FSM_TOTAL>>>(
        qkvh, qkvl, qkvh + BHS_, qkvl + BHS_, qkvh + 2 * BHS_, qkvl + 2 * BHS_, ah, al);

    Bias3 bout = { bo, bo, bo };
    mma_gemm<<<dim3(D_ / 128, M_ / 128, 1), 256, GSM_TOTAL>>>(
        ah, al, 0, wh + 3 * (size_t)NW_, wl + 3 * (size_t)NW_, 0, bout,
        nullptr, nullptr, 0, out, 0);
}

// round 9
// speedup vs baseline: 4.0392x; 1.0513x over previous
#include <cuda_runtime.h>
#include <cuda_fp16.h>
#include <math.h>
#include <stdint.h>

#define B_  2
#define S_  2048
#define D_  1024
#define H_  16
#define DK_ 64
#define M_  (B_ * S_)                 // 4096
#define NA_ (M_ * D_)                 // 4194304
#define NW_ (D_ * D_)                 // 1048576
#define BHS_ (B_ * H_ * S_ * DK_)     // 4194304

// ---------------------------------------------------------------------------
// Scratch (allocation-free rule: __device__ globals)
// ---------------------------------------------------------------------------
__device__ __half g_ah[3 * NA_];
__device__ __half g_al[3 * NA_];
__device__ __half g_wh[4 * NW_];
__device__ __half g_wl[4 * NW_];
__device__ __half g_qkvh[3 * BHS_];
__device__ __half g_qkvl[3 * BHS_];

struct Bias3 { const float* b0; const float* b1; const float* b2; };
struct In3   { const float* x0; const float* x1; const float* x2; };
struct In4   { const float* x0; const float* x1; const float* x2; const float* x3; };

// ---------------------------------------------------------------------------
// helpers
// ---------------------------------------------------------------------------
__device__ __forceinline__ uint32_t smem_u32(const void* p) {
    uint32_t a;
    asm("{ .reg .u64 t; cvta.to.shared.u64 t, %1; cvt.u32.u64 %0, t; }"
        : "=r"(a) : "l"(p));
    return a;
}
__device__ __forceinline__ void ldsm_x4(uint32_t addr, uint32_t* r) {
    asm volatile("ldmatrix.sync.aligned.m8n8.x4.shared.b16 {%0,%1,%2,%3}, [%4];"
        : "=r"(r[0]), "=r"(r[1]), "=r"(r[2]), "=r"(r[3]) : "r"(addr));
}
__device__ __forceinline__ void ldsm_x4_t(uint32_t addr, uint32_t* r) {
    asm volatile("ldmatrix.sync.aligned.m8n8.x4.trans.shared.b16 {%0,%1,%2,%3}, [%4];"
        : "=r"(r[0]), "=r"(r[1]), "=r"(r[2]), "=r"(r[3]) : "r"(addr));
}
__device__ __forceinline__ void mma16816(float* d, const uint32_t* a, const uint32_t* b) {
    asm volatile("mma.sync.aligned.m16n8k16.row.col.f32.f16.f16.f32 "
        "{%0,%1,%2,%3}, {%4,%5,%6,%7}, {%8,%9}, {%0,%1,%2,%3};"
        : "+f"(d[0]), "+f"(d[1]), "+f"(d[2]), "+f"(d[3])
        : "r"(a[0]), "r"(a[1]), "r"(a[2]), "r"(a[3]), "r"(b[0]), "r"(b[1]));
}
__device__ __forceinline__ void cp16(uint32_t d, const void* g) {
    asm volatile("cp.async.cg.shared.global [%0], [%1], 16;" :: "r"(d), "l"(g));
}
#define CP_COMMIT() asm volatile("cp.async.commit_group;")
#define CP_WAIT0()  asm volatile("cp.async.wait_group 0;")

__device__ __forceinline__ uint32_t swz64(uint32_t b)  { return b ^ ((b >> 3) & 0x30); }
__device__ __forceinline__ uint32_t swz128(uint32_t b) { return b ^ ((b >> 3) & 0x70); }
__device__ __forceinline__ void split1(float v, __half& h, __half& l) {
    h = __float2half_rn(v);
    l = __float2half_rn(v - __half2float(h));
}

// ---------------------------------------------------------------------------
// fused splits
// ---------------------------------------------------------------------------
__global__ __launch_bounds__(256) void split_qkv(In3 in, __half* __restrict__ hi,
                                                 __half* __restrict__ lo)
{
    int z = blockIdx.y;
    const float* x = (z == 0) ? in.x0 : (z == 1) ? in.x1 : in.x2;
    size_t off = (size_t)z * NA_;
    int i = (blockIdx.x * 256 + threadIdx.x) * 4;
    float4 v = *(const float4*)(x + i);
    __half h0, h1, h2, h3, l0, l1, l2, l3;
    split1(v.x, h0, l0); split1(v.y, h1, l1);
    split1(v.z, h2, l2); split1(v.w, h3, l3);
    __half2* hp = (__half2*)(hi + off + i);
    __half2* lp = (__half2*)(lo + off + i);
    hp[0] = __half2(h0, h1); hp[1] = __half2(h2, h3);
    lp[0] = __half2(l0, l1); lp[1] = __half2(l2, l3);
}

__global__ __launch_bounds__(256) void split_w(In4 in, __half* __restrict__ hi,
                                               __half* __restrict__ lo)
{
    int z = blockIdx.y;
    const float* x = (z == 0) ? in.x0 : (z == 1) ? in.x1 : (z == 2) ? in.x2 : in.x3;
    size_t off = (size_t)z * NW_;
    int i = (blockIdx.x * 256 + threadIdx.x) * 4;
    float4 v = *(const float4*)(x + i);
    __half h0, h1, h2, h3, l0, l1, l2, l3;
    split1(v.x, h0, l0); split1(v.y, h1, l1);
    split1(v.z, h2, l2); split1(v.w, h3, l3);
    __half2* hp = (__half2*)(hi + off + i);
    __half2* lp = (__half2*)(lo + off + i);
    hp[0] = __half2(h0, h1); hp[1] = __half2(h2, h3);
    lp[0] = __half2(l0, l1); lp[1] = __half2(l2, l3);
}

// ---------------------------------------------------------------------------
// Tensor-core GEMM (split fp16, cp.async 2-stage, batched over z).
// t2mask bit z => 2-term (Ah*Wh + Ah*Wl); else 3-term (+ Al*Wh).
// ---------------------------------------------------------------------------
#define GSM_STAGE 32768
#define GSM_TOTAL 65536

__global__ __launch_bounds__(256) void mma_gemm(
    const __half* __restrict__ Ah, const __half* __restrict__ Al,
    size_t strideA,
    const __half* __restrict__ Wh, const __half* __restrict__ Wl,
    size_t strideW, Bias3 bs, int t2mask,
    __half* __restrict__ Chi, __half* __restrict__ Clo, size_t strideC,
    float* __restrict__ Cf, int mode)
{
    extern __shared__ char sm[];
    const uint32_t sb = smem_u32(sm);
    const int tid = threadIdx.x;
    const int lane = tid & 31;
    const int wid = tid >> 5;
    const int z = blockIdx.z;
    const int bm = blockIdx.y * 128;
    const int bn = blockIdx.x * 128;
    const int wm = (wid & 1) * 64;
    const int wn = (wid >> 1) * 32;
    const bool two = (t2mask >> z) & 1;

    const float* bias = (z == 0) ? bs.b0 : (z == 1) ? bs.b1 : bs.b2;
    Ah += (size_t)z * strideA; Al += (size_t)z * strideA;
    Wh += (size_t)z * strideW; Wl += (size_t)z * strideW;

    float acc[4][4][4];
#pragma unroll
    for (int mt = 0; mt < 4; mt++)
#pragma unroll
        for (int nt = 0; nt < 4; nt++)
#pragma unroll
            for (int r = 0; r < 4; r++) acc[mt][nt][r] = 0.f;

    const int g = lane >> 3, r8 = lane & 7;
    uint32_t rowA[4], rowB[2];
#pragma unroll
    for (int mt = 0; mt < 4; mt++)
        rowA[mt] = (uint32_t)(wm + mt * 16 + (g & 1) * 8 + r8) * 64;
#pragma unroll
    for (int np = 0; np < 2; np++)
        rowB[np] = (uint32_t)(wn + np * 16 + (g >> 1) * 8 + r8) * 64;
    const uint32_t chA = (uint32_t)(g >> 1) * 16;
    const uint32_t chB = (uint32_t)(g & 1) * 16;

    const int gl_row0 = tid >> 2, gl_c0 = tid & 3;
    const int gl_row1 = (tid + 256) >> 2, gl_c1 = tid & 3;
    const uint32_t st0 = swz64((uint32_t)gl_row0 * 64 + gl_c0 * 16);
    const uint32_t st1 = swz64((uint32_t)gl_row1 * 64 + gl_c1 * 16);

    const __half* srcs[4] = { Ah, Al, Wh, Wl };
    const int rbase[4] = { bm, bm, bn, bn };

#pragma unroll
    for (int t = 0; t < 4; t++) {
        if (t == 1 && two) continue;
        const __half* s = srcs[t];
        cp16(sb + t * 8192 + st0, s + (size_t)(rbase[t] + gl_row0) * D_ + gl_c0 * 8);
        cp16(sb + t * 8192 + st1, s + (size_t)(rbase[t] + gl_row1) * D_ + gl_c1 * 8);
    }
    CP_COMMIT();

    for (int kt = 0; kt < 32; kt++) {
        const uint32_t stb = sb + (uint32_t)(kt & 1) * GSM_STAGE;
        CP_WAIT0();
        __syncthreads();

        if (kt + 1 < 32) {
            const int k0 = (kt + 1) * 32;
            const uint32_t nstb = sb + (uint32_t)((kt + 1) & 1) * GSM_STAGE;
#pragma unroll
            for (int t = 0; t < 4; t++) {
                if (t == 1 && two) continue;
                const __half* s = srcs[t];
                cp16(nstb + t * 8192 + st0, s + (size_t)(rbase[t] + gl_row0) * D_ + k0 + gl_c0 * 8);
                cp16(nstb + t * 8192 + st1, s + (size_t)(rbase[t] + gl_row1) * D_ + k0 + gl_c1 * 8);
            }
            CP_COMMIT();
        }

#pragma unroll
        for (int ks = 0; ks < 2; ks++) {
            const uint32_t kb = (uint32_t)ks * 32;
            uint32_t ah[4][4], al[4][4], bh[4][2], bl[4][2];
#pragma unroll
            for (int mt = 0; mt < 4; mt++) {
                uint32_t a = stb + swz64(rowA[mt] + kb + chA);
                ldsm_x4(a, ah[mt]);
                if (!two) ldsm_x4(a + 8192, al[mt]);
            }
#pragma unroll
            for (int np = 0; np < 2; np++) {
                uint32_t a = stb + 2 * 8192 + swz64(rowB[np] + kb + chB);
                uint32_t q[4];
                ldsm_x4(a, q);
                bh[2 * np][0] = q[0]; bh[2 * np][1] = q[1];
                bh[2 * np + 1][0] = q[2]; bh[2 * np + 1][1] = q[3];
                ldsm_x4(a + 8192, q);
                bl[2 * np][0] = q[0]; bl[2 * np][1] = q[1];
                bl[2 * np + 1][0] = q[2]; bl[2 * np + 1][1] = q[3];
            }
#pragma unroll
            for (int mt = 0; mt < 4; mt++)
#pragma unroll
                for (int nt = 0; nt < 4; nt++) {
                    mma16816(acc[mt][nt], ah[mt], bh[nt]);
                    mma16816(acc[mt][nt], ah[mt], bl[nt]);
                    if (!two) mma16816(acc[mt][nt], al[mt], bh[nt]);
                }
        }
    }

    const int fr = lane >> 2;
    const int fc = (lane & 3) * 2;
    Chi += (size_t)z * strideC; Clo += (size_t)z * strideC;
#pragma unroll
    for (int mt = 0; mt < 4; mt++) {
#pragma unroll
        for (int nt = 0; nt < 4; nt++) {
            int col = bn + wn + nt * 8 + fc;
            float bx = bias[col], by = bias[col + 1];
#pragma unroll
            for (int half = 0; half < 2; half++) {
                int row = bm + wm + mt * 16 + fr + half * 8;
                float vx = acc[mt][nt][2 * half] + bx;
                float vy = acc[mt][nt][2 * half + 1] + by;
                if (mode) {
                    int b = row >> 11, s = row & (S_ - 1);
                    int h = col >> 6, dk = col & 63;
                    size_t o = (((size_t)b * H_ + h) * S_ + s) * DK_ + dk;
                    __half hx, hy, lx, ly;
                    split1(vx, hx, lx); split1(vy, hy, ly);
                    *(__half2*)&Chi[o] = __half2(hx, hy);
                    *(__half2*)&Clo[o] = __half2(lx, ly);
                } else {
                    *(float2*)&Cf[(size_t)row * D_ + col] = make_float2(vx, vy);
                }
            }
        }
    }
}

// ---------------------------------------------------------------------------
// Flash attention, mma.sync fp16, causal, unscaled.
// QK^T: 3-term split. PV: 1-term (P fp16 x V-hi only).
// K ring 2x16KB (hi+lo), V ring 2x8KB (hi), Q 32KB. Total 80KB, 2 CTAs/SM.
// Writes ctx hi only (out-proj is 2-term on ctx-hi).
// ---------------------------------------------------------------------------
#define FQH 0
#define FQL 16384
#define FKS 32768            // K ring: 2 x 16384
#define FKSTG 16384
#define FVS 65536            // V ring: 2 x 8192
#define FVSTG 8192
#define FSM_TOTAL 81920

__global__ __launch_bounds__(256, 2) void flash_mma(
    const __half* __restrict__ Qh, const __half* __restrict__ Ql,
    const __half* __restrict__ Kh, const __half* __restrict__ Kl,
    const __half* __restrict__ Vh,
    __half* __restrict__ OutH)
{
    extern __shared__ char fsm[];
    const uint32_t sb = smem_u32(fsm);
    const int tid = threadIdx.x;
    const int lane = tid & 31;
    const int w = tid >> 5;
    const int qt = gridDim.x - 1 - blockIdx.x;     // long CTAs first
    const int h = blockIdx.y, b = blockIdx.z;
    const size_t base = ((size_t)b * H_ + h) * S_ * DK_;
    const int q0 = qt * 128;
    const int nkt = 2 * qt + 2;

    const __half* ksrc[2] = { Kh + base, Kl + base };
    const __half* vsrc = Vh + base;

    auto ldk = [&](uint32_t dst, int k0) {
#pragma unroll
        for (int t = 0; t < 2; t++)
#pragma unroll
            for (int half = 0; half < 2; half++) {
                int ci = half * 256 + tid;
                int row = ci >> 3, ch = ci & 7;
                cp16(dst + t * 8192 + swz128((uint32_t)row * 128 + ch * 16),
                     ksrc[t] + (size_t)(k0 + row) * DK_ + ch * 8);
            }
    };
    auto ldv = [&](uint32_t dst, int k0) {
#pragma unroll
        for (int half = 0; half < 2; half++) {
            int ci = half * 256 + tid;
            int row = ci >> 3, ch = ci & 7;
            cp16(dst + swz128((uint32_t)row * 128 + ch * 16),
                 vsrc + (size_t)(k0 + row) * DK_ + ch * 8);
        }
    };

    // ---- prologue: Q hi/lo + K(0) + V(0) ----
#pragma unroll
    for (int i = 0; i < 4; i++) {
        int idx = i * 256 + tid;
        int row = idx >> 3, ch = idx & 7;
        uint32_t sw = swz128((uint32_t)row * 128 + ch * 16);
        cp16(sb + FQH + sw, Qh + base + (size_t)(q0 + row) * DK_ + ch * 8);
        cp16(sb + FQL + sw, Ql + base + (size_t)(q0 + row) * DK_ + ch * 8);
    }
    ldk(sb + FKS, 0);
    ldv(sb + FVS, 0);
    CP_COMMIT();

    float o[8][4];
#pragma unroll
    for (int nt = 0; nt < 8; nt++)
#pragma unroll
        for (int r = 0; r < 4; r++) o[nt][r] = 0.f;
    float m0 = -INFINITY, m1 = -INFINITY, l0 = 0.f, l1 = 0.f;

    const int g = lane >> 3, r8 = lane & 7;
    const uint32_t qrow = (uint32_t)(w * 16 + (g & 1) * 8 + r8) * 128 + (uint32_t)(g >> 1) * 16;
    const uint32_t krow = (uint32_t)((g >> 1) * 8 + r8) * 128 + (uint32_t)(g & 1) * 16;
    const uint32_t vrow = (uint32_t)((lane & 7) + ((lane >> 3) & 1) * 8) * 128
                        + (uint32_t)(lane >> 4) * 16;
    const int wq = q0 + w * 16;

    for (int kt = 0; kt < nkt; kt++) {
        const int k0 = kt * 64;
        const uint32_t kstg = sb + FKS + (uint32_t)(kt & 1) * FKSTG;
        const uint32_t vstg = sb + FVS + (uint32_t)(kt & 1) * FVSTG;
        CP_WAIT0();
        __syncthreads();

        if (kt + 1 < nkt) {
            ldk(sb + FKS + (uint32_t)((kt + 1) & 1) * FKSTG, k0 + 64);
            ldv(sb + FVS + (uint32_t)((kt + 1) & 1) * FVSTG, k0 + 64);
            CP_COMMIT();
        }

        // ---- S = Q K^T (3-term) ----
        float s[8][4];
#pragma unroll
        for (int nt = 0; nt < 8; nt++)
#pragma unroll
            for (int r = 0; r < 4; r++) s[nt][r] = 0.f;

#pragma unroll
        for (int ks = 0; ks < 4; ks++) {
            uint32_t qh_f[4], ql_f[4];
            uint32_t qa = sb + FQH + swz128(qrow + (uint32_t)ks * 32);
            ldsm_x4(qa, qh_f);
            ldsm_x4(qa + (FQL - FQH), ql_f);
#pragma unroll
            for (int np = 0; np < 4; np++) {
                uint32_t ka = kstg + swz128(krow + (uint32_t)np * 2048 + (uint32_t)ks * 32);
                uint32_t rh[4], rl[4];
                ldsm_x4(ka, rh);
                ldsm_x4(ka + 8192, rl);
                uint32_t bh0[2] = { rh[0], rh[1] }, bh1[2] = { rh[2], rh[3] };
                uint32_t bl0[2] = { rl[0], rl[1] }, bl1[2] = { rl[2], rl[3] };
                mma16816(s[2 * np],     qh_f, bh0);
                mma16816(s[2 * np],     qh_f, bl0);
                mma16816(s[2 * np],     ql_f, bh0);
                mma16816(s[2 * np + 1], qh_f, bh1);
                mma16816(s[2 * np + 1], qh_f, bl1);
                mma16816(s[2 * np + 1], ql_f, bh1);
            }
        }

        if (k0 + 63 > wq) {
            int r0g = wq + (lane >> 2), r1g = r0g + 8;
            int cb = k0 + 2 * (lane & 3);
#pragma unroll
            for (int nt = 0; nt < 8; nt++) {
                int key = cb + nt * 8;
                if (key     > r0g) s[nt][0] = -1e9f;
                if (key + 1 > r0g) s[nt][1] = -1e9f;
                if (key     > r1g) s[nt][2] = -1e9f;
                if (key + 1 > r1g) s[nt][3] = -1e9f;
            }
        }

        // ---- online softmax ----
        float rm0 = -INFINITY, rm1 = -INFINITY;
#pragma unroll
        for (int nt = 0; nt < 8; nt++) {
            rm0 = fmaxf(rm0, fmaxf(s[nt][0], s[nt][1]));
            rm1 = fmaxf(rm1, fmaxf(s[nt][2], s[nt][3]));
        }
        rm0 = fmaxf(rm0, __shfl_xor_sync(0xffffffffu, rm0, 1));
        rm0 = fmaxf(rm0, __shfl_xor_sync(0xffffffffu, rm0, 2));
        rm1 = fmaxf(rm1, __shfl_xor_sync(0xffffffffu, rm1, 1));
        rm1 = fmaxf(rm1, __shfl_xor_sync(0xffffffffu, rm1, 2));
        float mn0 = fmaxf(m0, rm0), mn1 = fmaxf(m1, rm1);
        float sc0 = __expf(m0 - mn0), sc1 = __expf(m1 - mn1);
        float rs0 = 0.f, rs1 = 0.f;
#pragma unroll
        for (int nt = 0; nt < 8; nt++) {
            s[nt][0] = __expf(s[nt][0] - mn0);
            s[nt][1] = __expf(s[nt][1] - mn0);
            s[nt][2] = __expf(s[nt][2] - mn1);
            s[nt][3] = __expf(s[nt][3] - mn1);
            rs0 += s[nt][0] + s[nt][1];
            rs1 += s[nt][2] + s[nt][3];
        }
        rs0 += __shfl_xor_sync(0xffffffffu, rs0, 1);
        rs0 += __shfl_xor_sync(0xffffffffu, rs0, 2);
        rs1 += __shfl_xor_sync(0xffffffffu, rs1, 1);
        rs1 += __shfl_xor_sync(0xffffffffu, rs1, 2);
        l0 = l0 * sc0 + rs0; m0 = mn0;
        l1 = l1 * sc1 + rs1; m1 = mn1;
#pragma unroll
        for (int nt = 0; nt < 8; nt++) {
            o[nt][0] *= sc0; o[nt][1] *= sc0;
            o[nt][2] *= sc1; o[nt][3] *= sc1;
        }

        // ---- O += P V  (P fp16, V-hi only) ----
#pragma unroll
        for (int ks = 0; ks < 4; ks++) {
            uint32_t ap[4];
#pragma unroll
            for (int half = 0; half < 2; half++) {
                int st = 2 * ks + half;
                __half2 p01 = __floats2half2_rn(s[st][0], s[st][1]);
                __half2 p23 = __floats2half2_rn(s[st][2], s[st][3]);
                ap[2 * half]     = *(uint32_t*)&p01;
                ap[2 * half + 1] = *(uint32_t*)&p23;
            }
#pragma unroll
            for (int vb = 0; vb < 4; vb++) {
                uint32_t va = vstg + swz128(vrow + (uint32_t)ks * 2048 + (uint32_t)vb * 32);
                uint32_t rh[4];
                ldsm_x4_t(va, rh);
                uint32_t bh0[2] = { rh[0], rh[1] }, bh1[2] = { rh[2], rh[3] };
                mma16816(o[2 * vb],     ap, bh0);
                mma16816(o[2 * vb + 1], ap, bh1);
            }
        }
    }

    // ---- epilogue: ctx-hi fp16 at [b*S+s][h*64+dk] ----
    float inv0 = 1.f / l0, inv1 = 1.f / l1;
    int row0 = b * S_ + q0 + w * 16 + (lane >> 2);
    int row1 = row0 + 8;
    int colb = h * 64 + 2 * (lane & 3);
#pragma unroll
    for (int nt = 0; nt < 8; nt++) {
        int col = colb + nt * 8;
        *(__half2*)&OutH[(size_t)row0 * D_ + col] =
            __floats2half2_rn(o[nt][0] * inv0, o[nt][1] * inv0);
        *(__half2*)&OutH[(size_t)row1 * D_ + col] =
            __floats2half2_rn(o[nt][2] * inv1, o[nt][3] * inv1);
    }
}

// ---------------------------------------------------------------------------
extern "C" void kernel_launch(void* const* d_in, const int* in_sizes, int n_in,
                              void* d_out, int out_size)
{
    const float* Q  = (const float*)d_in[0];
    const float* K  = (const float*)d_in[1];
    const float* V  = (const float*)d_in[2];
    // d_in[3] = Mask (guaranteed tril -> hardcoded causal)
    const float* Wq = (const float*)d_in[4];
    const float* bq = (const float*)d_in[5];
    const float* Wk = (const float*)d_in[6];
    const float* bk = (const float*)d_in[7];
    const float* Wv = (const float*)d_in[8];
    const float* bv = (const float*)d_in[9];
    const float* Wo = (const float*)d_in[10];
    const float* bo = (const float*)d_in[11];
    float* out = (float*)d_out;

    __half *ah, *al, *wh, *wl, *qkvh, *qkvl;
    cudaGetSymbolAddress((void**)&ah, g_ah);
    cudaGetSymbolAddress((void**)&al, g_al);
    cudaGetSymbolAddress((void**)&wh, g_wh);
    cudaGetSymbolAddress((void**)&wl, g_wl);
    cudaGetSymbolAddress((void**)&qkvh, g_qkvh);
    cudaGetSymbolAddress((void**)&qkvl, g_qkvl);

    static bool attr_done = false;
    if (!attr_done) {
        cudaFuncSetAttribute(mma_gemm, cudaFuncAttributeMaxDynamicSharedMemorySize, GSM_TOTAL);
        cudaFuncSetAttribute(flash_mma, cudaFuncAttributeMaxDynamicSharedMemorySize, FSM_TOTAL);
        attr_done = true;
    }

    In4 ws = { Wq, Wk, Wv, Wo };
    split_w<<<dim3(NW_ / 1024, 4), 256>>>(ws, wh, wl);
    In3 xs = { Q, K, V };
    split_qkv<<<dim3(NA_ / 1024, 3), 256>>>(xs, ah, al);

    // QKV projections: Q,K 3-term, V 2-term (bit 2 set)
    Bias3 bqkv = { bq, bk, bv };
    mma_gemm<<<dim3(D_ / 128, M_ / 128, 3), 256, GSM_TOTAL>>>(
        ah, al, NA_, wh, wl, NW_, bqkv, 0b100, qkvh, qkvl, BHS_, nullptr, 1);

    // attention (ctx-hi into g_ah slot 0)
    flash_mma<<<dim3(S_ / 128, H_, B_), 256, FSM_TOTAL>>>(
        qkvh, qkvl, qkvh + BHS_, qkvl + BHS_, qkvh + 2 * BHS_, ah);

    // output projection: 2-term on ctx-hi
    Bias3 bout = { bo, bo, bo };
    mma_gemm<<<dim3(D_ / 128, M_ / 128, 1), 256, GSM_TOTAL>>>(
        ah, ah, 0, wh + 3 * (size_t)NW_, wl + 3 * (size_t)NW_, 0, bout, 0b1,
        nullptr, nullptr, 0, out, 0);
}

// round 10
// speedup vs baseline: 4.2425x; 1.0503x over previous
#include <cuda_runtime.h>
#include <cuda_fp16.h>
#include <math.h>
#include <stdint.h>

#define B_  2
#define S_  2048
#define D_  1024
#define H_  16
#define DK_ 64
#define M_  (B_ * S_)                 // 4096
#define NA_ (M_ * D_)                 // 4194304
#define NW_ (D_ * D_)                 // 1048576
#define BHS_ (B_ * H_ * S_ * DK_)     // 4194304

// ---------------------------------------------------------------------------
// Scratch (allocation-free rule: __device__ globals)
// ---------------------------------------------------------------------------
__device__ __half g_ah[3 * NA_];
__device__ __half g_al[3 * NA_];
__device__ __half g_wh[4 * NW_];
__device__ __half g_wl[4 * NW_];
__device__ __half g_qkvh[3 * BHS_];
__device__ __half g_qkvl[3 * BHS_];

struct Bias3 { const float* b0; const float* b1; const float* b2; };
struct In3   { const float* x0; const float* x1; const float* x2; };
struct In4   { const float* x0; const float* x1; const float* x2; const float* x3; };

// ---------------------------------------------------------------------------
// helpers
// ---------------------------------------------------------------------------
__device__ __forceinline__ uint32_t smem_u32(const void* p) {
    uint32_t a;
    asm("{ .reg .u64 t; cvta.to.shared.u64 t, %1; cvt.u32.u64 %0, t; }"
        : "=r"(a) : "l"(p));
    return a;
}
__device__ __forceinline__ void ldsm_x4(uint32_t addr, uint32_t* r) {
    asm volatile("ldmatrix.sync.aligned.m8n8.x4.shared.b16 {%0,%1,%2,%3}, [%4];"
        : "=r"(r[0]), "=r"(r[1]), "=r"(r[2]), "=r"(r[3]) : "r"(addr));
}
__device__ __forceinline__ void ldsm_x4_t(uint32_t addr, uint32_t* r) {
    asm volatile("ldmatrix.sync.aligned.m8n8.x4.trans.shared.b16 {%0,%1,%2,%3}, [%4];"
        : "=r"(r[0]), "=r"(r[1]), "=r"(r[2]), "=r"(r[3]) : "r"(addr));
}
__device__ __forceinline__ void mma16816(float* d, const uint32_t* a, const uint32_t* b) {
    asm volatile("mma.sync.aligned.m16n8k16.row.col.f32.f16.f16.f32 "
        "{%0,%1,%2,%3}, {%4,%5,%6,%7}, {%8,%9}, {%0,%1,%2,%3};"
        : "+f"(d[0]), "+f"(d[1]), "+f"(d[2]), "+f"(d[3])
        : "r"(a[0]), "r"(a[1]), "r"(a[2]), "r"(a[3]), "r"(b[0]), "r"(b[1]));
}
__device__ __forceinline__ void cp16(uint32_t d, const void* g) {
    asm volatile("cp.async.cg.shared.global [%0], [%1], 16;" :: "r"(d), "l"(g));
}
#define CP_COMMIT() asm volatile("cp.async.commit_group;")
#define CP_WAIT0()  asm volatile("cp.async.wait_group 0;")

__device__ __forceinline__ uint32_t swz64(uint32_t b)  { return b ^ ((b >> 3) & 0x30); }
__device__ __forceinline__ uint32_t swz128(uint32_t b) { return b ^ ((b >> 3) & 0x70); }
__device__ __forceinline__ void split1(float v, __half& h, __half& l) {
    h = __float2half_rn(v);
    l = __float2half_rn(v - __half2float(h));
}

// ---------------------------------------------------------------------------
// fused splits
// ---------------------------------------------------------------------------
__global__ __launch_bounds__(256) void split_qkv(In3 in, __half* __restrict__ hi,
                                                 __half* __restrict__ lo)
{
    int z = blockIdx.y;
    const float* x = (z == 0) ? in.x0 : (z == 1) ? in.x1 : in.x2;
    size_t off = (size_t)z * NA_;
    int i = (blockIdx.x * 256 + threadIdx.x) * 4;
    float4 v = *(const float4*)(x + i);
    __half h0, h1, h2, h3, l0, l1, l2, l3;
    split1(v.x, h0, l0); split1(v.y, h1, l1);
    split1(v.z, h2, l2); split1(v.w, h3, l3);
    __half2* hp = (__half2*)(hi + off + i);
    __half2* lp = (__half2*)(lo + off + i);
    hp[0] = __half2(h0, h1); hp[1] = __half2(h2, h3);
    lp[0] = __half2(l0, l1); lp[1] = __half2(l2, l3);
}

__global__ __launch_bounds__(256) void split_w(In4 in, __half* __restrict__ hi,
                                               __half* __restrict__ lo)
{
    int z = blockIdx.y;
    const float* x = (z == 0) ? in.x0 : (z == 1) ? in.x1 : (z == 2) ? in.x2 : in.x3;
    size_t off = (size_t)z * NW_;
    int i = (blockIdx.x * 256 + threadIdx.x) * 4;
    float4 v = *(const float4*)(x + i);
    __half h0, h1, h2, h3, l0, l1, l2, l3;
    split1(v.x, h0, l0); split1(v.y, h1, l1);
    split1(v.z, h2, l2); split1(v.w, h3, l3);
    __half2* hp = (__half2*)(hi + off + i);
    __half2* lp = (__half2*)(lo + off + i);
    hp[0] = __half2(h0, h1); hp[1] = __half2(h2, h3);
    lp[0] = __half2(l0, l1); lp[1] = __half2(l2, l3);
}

// ---------------------------------------------------------------------------
// Tensor-core GEMM (split fp16, cp.async 2-stage, batched over z).
// t2mask bit z => 2-term (skip Al*Wh). wlomask bit z => write Clo (mode 1).
// ---------------------------------------------------------------------------
#define GSM_STAGE 32768
#define GSM_TOTAL 65536

__global__ __launch_bounds__(256) void mma_gemm(
    const __half* __restrict__ Ah, const __half* __restrict__ Al,
    size_t strideA,
    const __half* __restrict__ Wh, const __half* __restrict__ Wl,
    size_t strideW, Bias3 bs, int t2mask, int wlomask,
    __half* __restrict__ Chi, __half* __restrict__ Clo, size_t strideC,
    float* __restrict__ Cf, int mode)
{
    extern __shared__ char sm[];
    const uint32_t sb = smem_u32(sm);
    const int tid = threadIdx.x;
    const int lane = tid & 31;
    const int wid = tid >> 5;
    const int z = blockIdx.z;
    const int bm = blockIdx.y * 128;
    const int bn = blockIdx.x * 128;
    const int wm = (wid & 1) * 64;
    const int wn = (wid >> 1) * 32;
    const bool two = (t2mask >> z) & 1;
    const bool wlo = (wlomask >> z) & 1;

    const float* bias = (z == 0) ? bs.b0 : (z == 1) ? bs.b1 : bs.b2;
    Ah += (size_t)z * strideA; Al += (size_t)z * strideA;
    Wh += (size_t)z * strideW; Wl += (size_t)z * strideW;

    float acc[4][4][4];
#pragma unroll
    for (int mt = 0; mt < 4; mt++)
#pragma unroll
        for (int nt = 0; nt < 4; nt++)
#pragma unroll
            for (int r = 0; r < 4; r++) acc[mt][nt][r] = 0.f;

    const int g = lane >> 3, r8 = lane & 7;
    uint32_t rowA[4], rowB[2];
#pragma unroll
    for (int mt = 0; mt < 4; mt++)
        rowA[mt] = (uint32_t)(wm + mt * 16 + (g & 1) * 8 + r8) * 64;
#pragma unroll
    for (int np = 0; np < 2; np++)
        rowB[np] = (uint32_t)(wn + np * 16 + (g >> 1) * 8 + r8) * 64;
    const uint32_t chA = (uint32_t)(g >> 1) * 16;
    const uint32_t chB = (uint32_t)(g & 1) * 16;

    const int gl_row0 = tid >> 2, gl_c0 = tid & 3;
    const int gl_row1 = (tid + 256) >> 2, gl_c1 = tid & 3;
    const uint32_t st0 = swz64((uint32_t)gl_row0 * 64 + gl_c0 * 16);
    const uint32_t st1 = swz64((uint32_t)gl_row1 * 64 + gl_c1 * 16);

    const __half* srcs[4] = { Ah, Al, Wh, Wl };
    const int rbase[4] = { bm, bm, bn, bn };

#pragma unroll
    for (int t = 0; t < 4; t++) {
        if (t == 1 && two) continue;
        const __half* s = srcs[t];
        cp16(sb + t * 8192 + st0, s + (size_t)(rbase[t] + gl_row0) * D_ + gl_c0 * 8);
        cp16(sb + t * 8192 + st1, s + (size_t)(rbase[t] + gl_row1) * D_ + gl_c1 * 8);
    }
    CP_COMMIT();

    for (int kt = 0; kt < 32; kt++) {
        const uint32_t stb = sb + (uint32_t)(kt & 1) * GSM_STAGE;
        CP_WAIT0();
        __syncthreads();

        if (kt + 1 < 32) {
            const int k0 = (kt + 1) * 32;
            const uint32_t nstb = sb + (uint32_t)((kt + 1) & 1) * GSM_STAGE;
#pragma unroll
            for (int t = 0; t < 4; t++) {
                if (t == 1 && two) continue;
                const __half* s = srcs[t];
                cp16(nstb + t * 8192 + st0, s + (size_t)(rbase[t] + gl_row0) * D_ + k0 + gl_c0 * 8);
                cp16(nstb + t * 8192 + st1, s + (size_t)(rbase[t] + gl_row1) * D_ + k0 + gl_c1 * 8);
            }
            CP_COMMIT();
        }

#pragma unroll
        for (int ks = 0; ks < 2; ks++) {
            const uint32_t kb = (uint32_t)ks * 32;
            uint32_t ah[4][4], al[4][4], bh[4][2], bl[4][2];
#pragma unroll
            for (int mt = 0; mt < 4; mt++) {
                uint32_t a = stb + swz64(rowA[mt] + kb + chA);
                ldsm_x4(a, ah[mt]);
                if (!two) ldsm_x4(a + 8192, al[mt]);
            }
#pragma unroll
            for (int np = 0; np < 2; np++) {
                uint32_t a = stb + 2 * 8192 + swz64(rowB[np] + kb + chB);
                uint32_t q[4];
                ldsm_x4(a, q);
                bh[2 * np][0] = q[0]; bh[2 * np][1] = q[1];
                bh[2 * np + 1][0] = q[2]; bh[2 * np + 1][1] = q[3];
                ldsm_x4(a + 8192, q);
                bl[2 * np][0] = q[0]; bl[2 * np][1] = q[1];
                bl[2 * np + 1][0] = q[2]; bl[2 * np + 1][1] = q[3];
            }
#pragma unroll
            for (int mt = 0; mt < 4; mt++)
#pragma unroll
                for (int nt = 0; nt < 4; nt++) {
                    mma16816(acc[mt][nt], ah[mt], bh[nt]);
                    mma16816(acc[mt][nt], ah[mt], bl[nt]);
                    if (!two) mma16816(acc[mt][nt], al[mt], bh[nt]);
                }
        }
    }

    const int fr = lane >> 2;
    const int fc = (lane & 3) * 2;
    Chi += (size_t)z * strideC; Clo += (size_t)z * strideC;
#pragma unroll
    for (int mt = 0; mt < 4; mt++) {
#pragma unroll
        for (int nt = 0; nt < 4; nt++) {
            int col = bn + wn + nt * 8 + fc;
            float bx = bias[col], by = bias[col + 1];
#pragma unroll
            for (int half = 0; half < 2; half++) {
                int row = bm + wm + mt * 16 + fr + half * 8;
                float vx = acc[mt][nt][2 * half] + bx;
                float vy = acc[mt][nt][2 * half + 1] + by;
                if (mode) {
                    int b = row >> 11, s = row & (S_ - 1);
                    int h = col >> 6, dk = col & 63;
                    size_t o = (((size_t)b * H_ + h) * S_ + s) * DK_ + dk;
                    __half hx, hy, lx, ly;
                    split1(vx, hx, lx); split1(vy, hy, ly);
                    *(__half2*)&Chi[o] = __half2(hx, hy);
                    if (wlo) *(__half2*)&Clo[o] = __half2(lx, ly);
                } else {
                    *(float2*)&Cf[(size_t)row * D_ + col] = make_float2(vx, vy);
                }
            }
        }
    }
}

// ---------------------------------------------------------------------------
// Flash attention, mma.sync fp16, causal, unscaled.
// QK^T: 2-term (Qh*Kh + Qh*Kl). PV: 1-term (P fp16 x V-hi).
// Q 16KB, K ring 2x16KB (hi+lo), V ring 2x8KB. Total 64KB, 2 CTAs/SM.
// ---------------------------------------------------------------------------
#define FQH 0
#define FKS 16384            // K ring: 2 x 16384
#define FKSTG 16384
#define FVS 49152            // V ring: 2 x 8192
#define FVSTG 8192
#define FSM_TOTAL 65536

__global__ __launch_bounds__(256, 2) void flash_mma(
    const __half* __restrict__ Qh,
    const __half* __restrict__ Kh, const __half* __restrict__ Kl,
    const __half* __restrict__ Vh,
    __half* __restrict__ OutH)
{
    extern __shared__ char fsm[];
    const uint32_t sb = smem_u32(fsm);
    const int tid = threadIdx.x;
    const int lane = tid & 31;
    const int w = tid >> 5;
    const int qt = gridDim.x - 1 - blockIdx.x;     // long CTAs first
    const int h = blockIdx.y, b = blockIdx.z;
    const size_t base = ((size_t)b * H_ + h) * S_ * DK_;
    const int q0 = qt * 128;
    const int nkt = 2 * qt + 2;

    const __half* ksrc[2] = { Kh + base, Kl + base };
    const __half* vsrc = Vh + base;

    auto ldk = [&](uint32_t dst, int k0) {
#pragma unroll
        for (int t = 0; t < 2; t++)
#pragma unroll
            for (int half = 0; half < 2; half++) {
                int ci = half * 256 + tid;
                int row = ci >> 3, ch = ci & 7;
                cp16(dst + t * 8192 + swz128((uint32_t)row * 128 + ch * 16),
                     ksrc[t] + (size_t)(k0 + row) * DK_ + ch * 8);
            }
    };
    auto ldv = [&](uint32_t dst, int k0) {
#pragma unroll
        for (int half = 0; half < 2; half++) {
            int ci = half * 256 + tid;
            int row = ci >> 3, ch = ci & 7;
            cp16(dst + swz128((uint32_t)row * 128 + ch * 16),
                 vsrc + (size_t)(k0 + row) * DK_ + ch * 8);
        }
    };

    // ---- prologue: Q-hi + K(0) + V(0) ----
#pragma unroll
    for (int i = 0; i < 4; i++) {
        int idx = i * 256 + tid;
        int row = idx >> 3, ch = idx & 7;
        cp16(sb + FQH + swz128((uint32_t)row * 128 + ch * 16),
             Qh + base + (size_t)(q0 + row) * DK_ + ch * 8);
    }
    ldk(sb + FKS, 0);
    ldv(sb + FVS, 0);
    CP_COMMIT();

    float o[8][4];
#pragma unroll
    for (int nt = 0; nt < 8; nt++)
#pragma unroll
        for (int r = 0; r < 4; r++) o[nt][r] = 0.f;
    float m0 = -INFINITY, m1 = -INFINITY, l0 = 0.f, l1 = 0.f;

    const int g = lane >> 3, r8 = lane & 7;
    const uint32_t qrow = (uint32_t)(w * 16 + (g & 1) * 8 + r8) * 128 + (uint32_t)(g >> 1) * 16;
    const uint32_t krow = (uint32_t)((g >> 1) * 8 + r8) * 128 + (uint32_t)(g & 1) * 16;
    const uint32_t vrow = (uint32_t)((lane & 7) + ((lane >> 3) & 1) * 8) * 128
                        + (uint32_t)(lane >> 4) * 16;
    const int wq = q0 + w * 16;

    for (int kt = 0; kt < nkt; kt++) {
        const int k0 = kt * 64;
        const uint32_t kstg = sb + FKS + (uint32_t)(kt & 1) * FKSTG;
        const uint32_t vstg = sb + FVS + (uint32_t)(kt & 1) * FVSTG;
        CP_WAIT0();
        __syncthreads();

        if (kt + 1 < nkt) {
            ldk(sb + FKS + (uint32_t)((kt + 1) & 1) * FKSTG, k0 + 64);
            ldv(sb + FVS + (uint32_t)((kt + 1) & 1) * FVSTG, k0 + 64);
            CP_COMMIT();
        }

        // ---- S = Q K^T (2-term: Qh*Kh + Qh*Kl) ----
        float s[8][4];
#pragma unroll
        for (int nt = 0; nt < 8; nt++)
#pragma unroll
            for (int r = 0; r < 4; r++) s[nt][r] = 0.f;

#pragma unroll
        for (int ks = 0; ks < 4; ks++) {
            uint32_t qh_f[4];
            ldsm_x4(sb + FQH + swz128(qrow + (uint32_t)ks * 32), qh_f);
#pragma unroll
            for (int np = 0; np < 4; np++) {
                uint32_t ka = kstg + swz128(krow + (uint32_t)np * 2048 + (uint32_t)ks * 32);
                uint32_t rh[4], rl[4];
                ldsm_x4(ka, rh);
                ldsm_x4(ka + 8192, rl);
                uint32_t bh0[2] = { rh[0], rh[1] }, bh1[2] = { rh[2], rh[3] };
                uint32_t bl0[2] = { rl[0], rl[1] }, bl1[2] = { rl[2], rl[3] };
                mma16816(s[2 * np],     qh_f, bh0);
                mma16816(s[2 * np],     qh_f, bl0);
                mma16816(s[2 * np + 1], qh_f, bh1);
                mma16816(s[2 * np + 1], qh_f, bl1);
            }
        }

        if (k0 + 63 > wq) {
            int r0g = wq + (lane >> 2), r1g = r0g + 8;
            int cb = k0 + 2 * (lane & 3);
#pragma unroll
            for (int nt = 0; nt < 8; nt++) {
                int key = cb + nt * 8;
                if (key     > r0g) s[nt][0] = -1e9f;
                if (key + 1 > r0g) s[nt][1] = -1e9f;
                if (key     > r1g) s[nt][2] = -1e9f;
                if (key + 1 > r1g) s[nt][3] = -1e9f;
            }
        }

        // ---- online softmax ----
        float rm0 = -INFINITY, rm1 = -INFINITY;
#pragma unroll
        for (int nt = 0; nt < 8; nt++) {
            rm0 = fmaxf(rm0, fmaxf(s[nt][0], s[nt][1]));
            rm1 = fmaxf(rm1, fmaxf(s[nt][2], s[nt][3]));
        }
        rm0 = fmaxf(rm0, __shfl_xor_sync(0xffffffffu, rm0, 1));
        rm0 = fmaxf(rm0, __shfl_xor_sync(0xffffffffu, rm0, 2));
        rm1 = fmaxf(rm1, __shfl_xor_sync(0xffffffffu, rm1, 1));
        rm1 = fmaxf(rm1, __shfl_xor_sync(0xffffffffu, rm1, 2));
        float mn0 = fmaxf(m0, rm0), mn1 = fmaxf(m1, rm1);
        float sc0 = __expf(m0 - mn0), sc1 = __expf(m1 - mn1);
        float rs0 = 0.f, rs1 = 0.f;
#pragma unroll
        for (int nt = 0; nt < 8; nt++) {
            s[nt][0] = __expf(s[nt][0] - mn0);
            s[nt][1] = __expf(s[nt][1] - mn0);
            s[nt][2] = __expf(s[nt][2] - mn1);
            s[nt][3] = __expf(s[nt][3] - mn1);
            rs0 += s[nt][0] + s[nt][1];
            rs1 += s[nt][2] + s[nt][3];
        }
        rs0 += __shfl_xor_sync(0xffffffffu, rs0, 1);
        rs0 += __shfl_xor_sync(0xffffffffu, rs0, 2);
        rs1 += __shfl_xor_sync(0xffffffffu, rs1, 1);
        rs1 += __shfl_xor_sync(0xffffffffu, rs1, 2);
        l0 = l0 * sc0 + rs0; m0 = mn0;
        l1 = l1 * sc1 + rs1; m1 = mn1;
#pragma unroll
        for (int nt = 0; nt < 8; nt++) {
            o[nt][0] *= sc0; o[nt][1] *= sc0;
            o[nt][2] *= sc1; o[nt][3] *= sc1;
        }

        // ---- O += P V  (P fp16, V-hi) ----
#pragma unroll
        for (int ks = 0; ks < 4; ks++) {
            uint32_t ap[4];
#pragma unroll
            for (int half = 0; half < 2; half++) {
                int st = 2 * ks + half;
                __half2 p01 = __floats2half2_rn(s[st][0], s[st][1]);
                __half2 p23 = __floats2half2_rn(s[st][2], s[st][3]);
                ap[2 * half]     = *(uint32_t*)&p01;
                ap[2 * half + 1] = *(uint32_t*)&p23;
            }
#pragma unroll
            for (int vb = 0; vb < 4; vb++) {
                uint32_t va = vstg + swz128(vrow + (uint32_t)ks * 2048 + (uint32_t)vb * 32);
                uint32_t rh[4];
                ldsm_x4_t(va, rh);
                uint32_t bh0[2] = { rh[0], rh[1] }, bh1[2] = { rh[2], rh[3] };
                mma16816(o[2 * vb],     ap, bh0);
                mma16816(o[2 * vb + 1], ap, bh1);
            }
        }
    }

    // ---- epilogue: ctx-hi fp16 at [b*S+s][h*64+dk] ----
    float inv0 = 1.f / l0, inv1 = 1.f / l1;
    int row0 = b * S_ + q0 + w * 16 + (lane >> 2);
    int row1 = row0 + 8;
    int colb = h * 64 + 2 * (lane & 3);
#pragma unroll
    for (int nt = 0; nt < 8; nt++) {
        int col = colb + nt * 8;
        *(__half2*)&OutH[(size_t)row0 * D_ + col] =
            __floats2half2_rn(o[nt][0] * inv0, o[nt][1] * inv0);
        *(__half2*)&OutH[(size_t)row1 * D_ + col] =
            __floats2half2_rn(o[nt][2] * inv1, o[nt][3] * inv1);
    }
}

// ---------------------------------------------------------------------------
extern "C" void kernel_launch(void* const* d_in, const int* in_sizes, int n_in,
                              void* d_out, int out_size)
{
    const float* Q  = (const float*)d_in[0];
    const float* K  = (const float*)d_in[1];
    const float* V  = (const float*)d_in[2];
    // d_in[3] = Mask (guaranteed tril -> hardcoded causal)
    const float* Wq = (const float*)d_in[4];
    const float* bq = (const float*)d_in[5];
    const float* Wk = (const float*)d_in[6];
    const float* bk = (const float*)d_in[7];
    const float* Wv = (const float*)d_in[8];
    const float* bv = (const float*)d_in[9];
    const float* Wo = (const float*)d_in[10];
    const float* bo = (const float*)d_in[11];
    float* out = (float*)d_out;

    __half *ah, *al, *wh, *wl, *qkvh, *qkvl;
    cudaGetSymbolAddress((void**)&ah, g_ah);
    cudaGetSymbolAddress((void**)&al, g_al);
    cudaGetSymbolAddress((void**)&wh, g_wh);
    cudaGetSymbolAddress((void**)&wl, g_wl);
    cudaGetSymbolAddress((void**)&qkvh, g_qkvh);
    cudaGetSymbolAddress((void**)&qkvl, g_qkvl);

    static bool attr_done = false;
    if (!attr_done) {
        cudaFuncSetAttribute(mma_gemm, cudaFuncAttributeMaxDynamicSharedMemorySize, GSM_TOTAL);
        cudaFuncSetAttribute(flash_mma, cudaFuncAttributeMaxDynamicSharedMemorySize, FSM_TOTAL);
        attr_done = true;
    }

    In4 ws = { Wq, Wk, Wv, Wo };
    split_w<<<dim3(NW_ / 1024, 4), 256>>>(ws, wh, wl);
    In3 xs = { Q, K, V };
    split_qkv<<<dim3(NA_ / 1024, 3), 256>>>(xs, ah, al);

    // QKV projections: Q,K 3-term, V 2-term; only K writes lo output
    Bias3 bqkv = { bq, bk, bv };
    mma_gemm<<<dim3(D_ / 128, M_ / 128, 3), 256, GSM_TOTAL>>>(
        ah, al, NA_, wh, wl, NW_, bqkv, 0b100, 0b010, qkvh, qkvl, BHS_, nullptr, 1);

    // attention (ctx-hi into g_ah slot 0); Ql no longer consumed
    flash_mma<<<dim3(S_ / 128, H_, B_), 256, FSM_TOTAL>>>(
        qkvh, qkvh + BHS_, qkvl + BHS_, qkvh + 2 * BHS_, ah);

    // output projection: 2-term on ctx-hi
    Bias3 bout = { bo, bo, bo };
    mma_gemm<<<dim3(D_ / 128, M_ / 128, 1), 256, GSM_TOTAL>>>(
        ah, ah, 0, wh + 3 * (size_t)NW_, wl + 3 * (size_t)NW_, 0, bout, 0b1, 0,
        nullptr, nullptr, 0, out, 0);
}